// round 2
// baseline (speedup 1.0000x reference)
#include <cuda_runtime.h>
#include <math.h>

#define Bd 16
#define Sd 168
#define Nd 200
#define Hd 128
#define Td 24
#define NHd 4
#define DHd 32

#define R_KV (Bd*Sd*Nd)      /* 537600 */
#define R_Q  (Bd*Td*Nd)      /* 76800  */

// ---------------- scratch (static device allocations; no cudaMalloc) ----------------
__device__ float g_query[R_Q*Hd];
__device__ float g_Q[R_Q*Hd];
__device__ float g_KV[(size_t)R_KV*256];   // K in cols 0..127, V in cols 128..255
__device__ float g_ctx[R_Q*Hd];
__device__ float g_comb[R_Q*Hd];
__device__ float g_xln[R_Q*Hd];
__device__ float g_gates[R_Q*512];
__device__ float g_x1[R_Q*Hd];
__device__ float g_x2[R_Q*Hd];
__device__ float g_hWh[Bd*Nd*512];
__device__ float g_G0[Bd*Nd*512];
__device__ float g_G1[Bd*Nd*512];
__device__ float g_Wkv[128*256];
__device__ float g_bkv[256];
__device__ float g_Wcc[128*128];
__device__ float g_bcc[128];

// ---------------- packed fp32x2 FMA (doubles fp32 throughput on sm_103a) ----------------
__device__ __forceinline__ float2 ffma2(float2 a, float2 b, float2 c) {
    float2 d;
    asm("fma.rn.f32x2 %0, %1, %2, %3;"
        : "=l"(*reinterpret_cast<unsigned long long*>(&d))
        : "l"(*reinterpret_cast<unsigned long long*>(&a)),
          "l"(*reinterpret_cast<unsigned long long*>(&b)),
          "l"(*reinterpret_cast<unsigned long long*>(&c)));
    return d;
}

__device__ __forceinline__ float sigmoidf_(float x) { return 1.f / (1.f + expf(-x)); }

// ---------------- SGEMM 128x128 tile, BK=8, 256 threads, 8x8 microtile, double-buffered ----------------
// C[M x Nc] = A[M x K] * Bw[K x Nc] (+ bias) (+= if ACC). All dims multiples of tile sizes.
template<bool ACC>
__global__ void __launch_bounds__(256, 2) sgemm_kernel(
    const float* __restrict__ A, const float* __restrict__ Bw,
    float* __restrict__ C, const float* __restrict__ bias,
    int K, int ldb)
{
    __shared__ float As[2][8][128];
    __shared__ float Bs[2][8][128];
    const int tid  = threadIdx.x;
    const int row0 = blockIdx.y * 128;
    const int col0 = blockIdx.x * 128;
    const int arow = tid >> 1;
    const int ak   = (tid & 1) << 2;
    const int brow = tid >> 5;
    const int bcol = (tid & 31) << 2;
    const float* Ap = A + (size_t)(row0 + arow) * K + ak;
    const float* Bp = Bw + (size_t)brow * ldb + col0 + bcol;

    float4 av = *(const float4*)Ap;
    float4 bv = *(const float4*)Bp;
    As[0][ak+0][arow] = av.x; As[0][ak+1][arow] = av.y;
    As[0][ak+2][arow] = av.z; As[0][ak+3][arow] = av.w;
    *(float4*)&Bs[0][brow][bcol] = bv;
    __syncthreads();

    const int ty = tid >> 4;
    const int tx = tid & 15;
    float2 acc[8][4];
    #pragma unroll
    for (int i = 0; i < 8; i++)
        #pragma unroll
        for (int j = 0; j < 4; j++) acc[i][j] = make_float2(0.f, 0.f);

    const int nk = K >> 3;
    for (int kt = 0; kt < nk; kt++) {
        const int cur = kt & 1;
        if (kt + 1 < nk) {
            av = *(const float4*)(Ap + (kt + 1) * 8);
            bv = *(const float4*)(Bp + (size_t)(kt + 1) * 8 * ldb);
        }
        #pragma unroll
        for (int kk = 0; kk < 8; kk++) {
            float4 a0 = *(const float4*)&As[cur][kk][ty*8];
            float4 a1 = *(const float4*)&As[cur][kk][ty*8+4];
            float4 b0 = *(const float4*)&Bs[cur][kk][tx*8];
            float4 b1 = *(const float4*)&Bs[cur][kk][tx*8+4];
            float a[8] = {a0.x,a0.y,a0.z,a0.w,a1.x,a1.y,a1.z,a1.w};
            float2 bp[4] = {make_float2(b0.x,b0.y), make_float2(b0.z,b0.w),
                            make_float2(b1.x,b1.y), make_float2(b1.z,b1.w)};
            #pragma unroll
            for (int i = 0; i < 8; i++) {
                float2 aa = make_float2(a[i], a[i]);
                #pragma unroll
                for (int j = 0; j < 4; j++) acc[i][j] = ffma2(aa, bp[j], acc[i][j]);
            }
        }
        if (kt + 1 < nk) {
            const int nxt = cur ^ 1;
            As[nxt][ak+0][arow] = av.x; As[nxt][ak+1][arow] = av.y;
            As[nxt][ak+2][arow] = av.z; As[nxt][ak+3][arow] = av.w;
            *(float4*)&Bs[nxt][brow][bcol] = bv;
        }
        __syncthreads();
    }

    float bvals[8];
    if (bias) {
        #pragma unroll
        for (int j = 0; j < 8; j++) bvals[j] = bias[col0 + tx*8 + j];
    } else {
        #pragma unroll
        for (int j = 0; j < 8; j++) bvals[j] = 0.f;
    }
    #pragma unroll
    for (int i = 0; i < 8; i++) {
        float* Cp = C + (size_t)(row0 + ty*8 + i) * ldb + col0 + tx*8;
        float4 o0, o1;
        o0.x = acc[i][0].x + bvals[0]; o0.y = acc[i][0].y + bvals[1];
        o0.z = acc[i][1].x + bvals[2]; o0.w = acc[i][1].y + bvals[3];
        o1.x = acc[i][2].x + bvals[4]; o1.y = acc[i][2].y + bvals[5];
        o1.z = acc[i][3].x + bvals[6]; o1.w = acc[i][3].y + bvals[7];
        if (ACC) {
            float4 c0v = *(const float4*)Cp;
            float4 c1v = *(const float4*)(Cp + 4);
            o0.x += c0v.x; o0.y += c0v.y; o0.z += c0v.z; o0.w += c0v.w;
            o1.x += c1v.x; o1.y += c1v.y; o1.z += c1v.z; o1.w += c1v.w;
        }
        *(float4*)Cp = o0;
        *(float4*)(Cp + 4) = o1;
    }
}

// ---------------- small prep kernels ----------------
__global__ void fuse_wkv_kernel(const float* __restrict__ Wk, const float* __restrict__ Wv,
                                const float* __restrict__ bk, const float* __restrict__ bv) {
    int idx = blockIdx.x * blockDim.x + threadIdx.x;
    if (idx < 128 * 256) {
        int k = idx >> 8, c = idx & 255;
        g_Wkv[idx] = (c < 128) ? Wk[k*128 + c] : Wv[k*128 + (c - 128)];
    }
    if (idx < 256) g_bkv[idx] = (idx < 128) ? bk[idx] : bv[idx - 128];
}

__global__ void bcc_kernel(const float* __restrict__ bo, const float* __restrict__ ctxW,
                           const float* __restrict__ ctxb) {
    int c = threadIdx.x;  // 128 threads
    float s = ctxb[c];
    for (int k = 0; k < 128; k++) s += bo[k] * ctxW[(128 + k) * 128 + c];
    g_bcc[c] = s;
}

__global__ void build_query_kernel(const float* __restrict__ sq, const float* __restrict__ h1) {
    int i = blockIdx.x * blockDim.x + threadIdx.x;  // float4 index
    if (i >= R_Q * Hd / 4) return;
    int c4 = (i & 31) << 2;
    int r  = i >> 5;
    int t  = (r / Nd) % Td;
    int b  = r / (Td * Nd);
    int n  = r % Nd;
    float4 a  = *(const float4*)(sq + t * Hd + c4);
    float4 hh = *(const float4*)(h1 + ((size_t)(b * Nd + n)) * Hd + c4);
    *(float4*)(g_query + (size_t)r * Hd + c4) =
        make_float4(a.x + hh.x, a.y + hh.y, a.z + hh.z, a.w + hh.w);
}

// ---------------- attention: one block per (b,n) ----------------
// smem: sQ 24x132, sK/sV 168x132 (stride 132 => +4 banks/row, float4-aligned), sS 96x168
#define ATTN_SMEM ((24*132 + 168*132 + 96*168) * 4)

__global__ void __launch_bounds__(256) attn_kernel(
    const float* __restrict__ Q, const float* __restrict__ KV,
    float* __restrict__ attn_out, float* __restrict__ ctx_out)
{
    const int n = blockIdx.x;
    const int b = blockIdx.y;
    extern __shared__ float sm[];
    float* sQ = sm;               // 24*132
    float* sK = sm + 24*132;      // 168*132 (K then reused for V)
    float* sS = sK + 168*132;     // 96*168
    const int tid = threadIdx.x;

    {   // load Q rows for this (b,n)
        const float* qb = Q + ((size_t)(b * Td) * Nd + n) * Hd;
        for (int i = tid; i < Td * 32; i += 256) {
            int t = i >> 5, c4 = (i & 31) << 2;
            *(float4*)&sQ[t*132 + c4] = *(const float4*)(qb + (size_t)t * Nd * Hd + c4);
        }
    }
    {   // load K
        const float* kb = KV + ((size_t)(b * Sd) * Nd + n) * 256;
        for (int i = tid; i < Sd * 32; i += 256) {
            int s = i >> 5, c4 = (i & 31) << 2;
            *(float4*)&sK[s*132 + c4] = *(const float4*)(kb + (size_t)s * Nd * 256 + c4);
        }
    }
    __syncthreads();

    // ---- scores: per head group (64 thr) an 8x8 thread grid, 3t x 21s per thread ----
    {
        const int hg  = tid >> 6;
        const int i_t = (tid >> 3) & 7;
        const int j_s = tid & 7;
        float acc[3][21];
        #pragma unroll
        for (int a = 0; a < 3; a++)
            #pragma unroll
            for (int c = 0; c < 21; c++) acc[a][c] = 0.f;
        #pragma unroll
        for (int d4 = 0; d4 < 8; d4++) {
            float4 q[3];
            #pragma unroll
            for (int a = 0; a < 3; a++)
                q[a] = *(const float4*)&sQ[(i_t + 8*a)*132 + hg*32 + d4*4];
            #pragma unroll
            for (int c = 0; c < 21; c++) {
                float4 k = *(const float4*)&sK[(j_s + 8*c)*132 + hg*32 + d4*4];
                #pragma unroll
                for (int a = 0; a < 3; a++)
                    acc[a][c] += q[a].x*k.x + q[a].y*k.y + q[a].z*k.z + q[a].w*k.w;
            }
        }
        const float scale = 0.17677669529663687f;  // 1/sqrt(32)
        #pragma unroll
        for (int a = 0; a < 3; a++)
            #pragma unroll
            for (int c = 0; c < 21; c++)
                sS[((i_t + 8*a)*4 + hg)*168 + (j_s + 8*c)] = acc[a][c] * scale;
    }
    __syncthreads();

    {   // load V into sK (scores no longer need K); softmax below only touches sS
        const float* vb = KV + ((size_t)(b * Sd) * Nd + n) * 256 + 128;
        for (int i = tid; i < Sd * 32; i += 256) {
            int s = i >> 5, c4 = (i & 31) << 2;
            *(float4*)&sK[s*132 + c4] = *(const float4*)(vb + (size_t)s * Nd * 256 + c4);
        }
    }

    // ---- softmax over s (168) for 96 rows; write attn to GMEM + normalize sS ----
    {
        const int w = tid >> 5, lane = tid & 31;
        for (int rr = 0; rr < 12; rr++) {
            int row = w + (rr << 3);
            float* Sr = sS + row * 168;
            float vals[6];
            float vmax = -1e30f;
            #pragma unroll
            for (int k = 0; k < 6; k++) {
                int s = lane + (k << 5);
                vals[k] = (s < 168) ? Sr[s] : -1e30f;
                vmax = fmaxf(vmax, vals[k]);
            }
            #pragma unroll
            for (int o = 16; o > 0; o >>= 1) vmax = fmaxf(vmax, __shfl_xor_sync(~0u, vmax, o));
            float sum = 0.f;
            #pragma unroll
            for (int k = 0; k < 6; k++) {
                int s = lane + (k << 5);
                float e = (s < 168) ? expf(vals[k] - vmax) : 0.f;
                vals[k] = e; sum += e;
            }
            #pragma unroll
            for (int o = 16; o > 0; o >>= 1) sum += __shfl_xor_sync(~0u, sum, o);
            float inv = 1.f / sum;
            int t = row >> 2, h = row & 3;
            float* outp = attn_out + ((((size_t)(b * Td + t) * NHd + h) * Nd + n) * Sd);
            #pragma unroll
            for (int k = 0; k < 6; k++) {
                int s = lane + (k << 5);
                if (s < 168) { float p = vals[k] * inv; Sr[s] = p; outp[s] = p; }
            }
        }
    }
    __syncthreads();

    // ---- ctx = attn @ V : thread tile 3t x 4c ----
    {
        const int cq = tid & 31;
        const int tg = tid >> 5;
        const int c0 = cq << 2;
        const int h  = c0 >> 5;
        float acc2[3][4];
        #pragma unroll
        for (int a = 0; a < 3; a++)
            #pragma unroll
            for (int j = 0; j < 4; j++) acc2[a][j] = 0.f;
        #pragma unroll 4
        for (int s = 0; s < 168; s++) {
            float4 v = *(const float4*)&sK[s*132 + c0];
            #pragma unroll
            for (int a = 0; a < 3; a++) {
                int t = tg + (a << 3);
                float p = sS[(t*4 + h)*168 + s];
                acc2[a][0] += p * v.x; acc2[a][1] += p * v.y;
                acc2[a][2] += p * v.z; acc2[a][3] += p * v.w;
            }
        }
        #pragma unroll
        for (int a = 0; a < 3; a++) {
            int t = tg + (a << 3);
            *(float4*)(ctx_out + ((size_t)(b * Td + t) * Nd + n) * Hd + c0) =
                make_float4(acc2[a][0], acc2[a][1], acc2[a][2], acc2[a][3]);
        }
    }
}

// ---------------- layernorm: one warp per 128-wide row ----------------
__global__ void ln_kernel(const float* __restrict__ x, const float* __restrict__ g,
                          const float* __restrict__ bt, float* __restrict__ y) {
    int w = threadIdx.x >> 5, lane = threadIdx.x & 31;
    int row = blockIdx.x * 8 + w;
    const float* xr = x + (size_t)row * 128;
    float4 v = *(const float4*)(xr + lane * 4);
    float s  = v.x + v.y + v.z + v.w;
    float sq = v.x*v.x + v.y*v.y + v.z*v.z + v.w*v.w;
    #pragma unroll
    for (int o = 16; o > 0; o >>= 1) {
        s  += __shfl_xor_sync(~0u, s,  o);
        sq += __shfl_xor_sync(~0u, sq, o);
    }
    float m   = s * (1.f / 128.f);
    float var = sq * (1.f / 128.f) - m * m;
    float inv = rsqrtf(var + 1e-5f);
    float4 gg = *(const float4*)(g + lane * 4);
    float4 bb = *(const float4*)(bt + lane * 4);
    float4 o4;
    o4.x = (v.x - m) * inv * gg.x + bb.x;
    o4.y = (v.y - m) * inv * gg.y + bb.y;
    o4.z = (v.z - m) * inv * gg.z + bb.z;
    o4.w = (v.w - m) * inv * gg.w + bb.w;
    *(float4*)(y + (size_t)row * 128 + lane * 4) = o4;
}

// ---------------- G[b,m,:] = sum_n adj[m,n]*hWh[b,n,:] + bias ----------------
__global__ void agg_kernel(const float* __restrict__ adj, const float* __restrict__ hWh,
                           const float* __restrict__ bv, float* __restrict__ G) {
    __shared__ float sA[8][200];
    int b = blockIdx.y, m0 = blockIdx.x * 8;
    int tid = threadIdx.x;  // 512
    for (int i = tid; i < 8 * 200; i += 512) {
        int m = i / 200, nn = i % 200;
        sA[m][nn] = adj[(m0 + m) * 200 + nn];
    }
    __syncthreads();
    int c = tid;
    float acc[8];
    #pragma unroll
    for (int m = 0; m < 8; m++) acc[m] = 0.f;
    const float* hb = hWh + (size_t)b * 200 * 512 + c;
    for (int nn = 0; nn < 200; nn++) {
        float v = hb[(size_t)nn * 512];
        #pragma unroll
        for (int m = 0; m < 8; m++) acc[m] += sA[m][nn] * v;
    }
    float bb = bv[c];
    #pragma unroll
    for (int m = 0; m < 8; m++)
        G[((size_t)b * 200 + m0 + m) * 512 + c] = acc[m] + bb;
}

// ---------------- fused LSTM activation (+ broadcast gate bias, + optional residual) ----------------
__global__ void act_kernel(const float* __restrict__ gates, const float* __restrict__ G,
                           const float* __restrict__ cin, const float* __restrict__ resid,
                           float* __restrict__ xout) {
    int idx = blockIdx.x * blockDim.x + threadIdx.x;
    if (idx >= R_Q * Hd) return;
    int h = idx & 127;
    int r = idx >> 7;
    int b = r / (Td * Nd);
    int n = r % Nd;
    size_t gb = ((size_t)(b * Nd) + n) * 512 + h;
    size_t gr = (size_t)r * 512 + h;
    float i_ = gates[gr]        + G[gb];
    float f_ = gates[gr + 128]  + G[gb + 128];
    float g_ = gates[gr + 256]  + G[gb + 256];
    float o_ = gates[gr + 384]  + G[gb + 384];
    float c  = cin[((size_t)(b * Nd) + n) * 128 + h];
    float cn = sigmoidf_(f_) * c + sigmoidf_(i_) * tanhf(g_);
    float x  = sigmoidf_(o_) * tanhf(cn);
    if (resid) x += resid[idx];
    xout[idx] = x;
}

// ---------------- preds: warp-per-row dot with out_W ----------------
__global__ void preds_kernel(const float* __restrict__ x2, const float* __restrict__ W,
                             const float* __restrict__ ob, float* __restrict__ out) {
    int w = threadIdx.x >> 5, lane = threadIdx.x & 31;
    int r = blockIdx.x * 8 + w;
    float4 v  = *(const float4*)(x2 + (size_t)r * 128 + lane * 4);
    float4 ww = *(const float4*)(W + lane * 4);
    float s = v.x*ww.x + v.y*ww.y + v.z*ww.z + v.w*ww.w;
    #pragma unroll
    for (int o = 16; o > 0; o >>= 1) s += __shfl_xor_sync(~0u, s, o);
    if (lane == 0) out[r] = s + ob[0];
}

// ---------------- launch ----------------
extern "C" void kernel_launch(void* const* d_in, const int* in_sizes, int n_in,
                              void* d_out, int out_size) {
    const float* enc  = (const float*)d_in[0];
    const float* h0   = (const float*)d_in[1];
    const float* c0   = (const float*)d_in[2];
    const float* h1   = (const float*)d_in[3];
    const float* c1   = (const float*)d_in[4];
    const float* adj  = (const float*)d_in[5];
    const float* sq   = (const float*)d_in[6];
    const float* Wq   = (const float*)d_in[7];
    const float* bq   = (const float*)d_in[8];
    const float* Wk   = (const float*)d_in[9];
    const float* bk   = (const float*)d_in[10];
    const float* Wv   = (const float*)d_in[11];
    const float* bv   = (const float*)d_in[12];
    const float* Wo   = (const float*)d_in[13];
    const float* bo   = (const float*)d_in[14];
    const float* ctxW = (const float*)d_in[15];
    const float* ctxb = (const float*)d_in[16];
    const float* Wx0  = (const float*)d_in[17];
    const float* Wh0  = (const float*)d_in[18];
    const float* b0   = (const float*)d_in[19];
    const float* lng0 = (const float*)d_in[20];
    const float* lnb0 = (const float*)d_in[21];
    const float* Wx1  = (const float*)d_in[22];
    const float* Wh1  = (const float*)d_in[23];
    const float* b1   = (const float*)d_in[24];
    const float* lng1 = (const float*)d_in[25];
    const float* lnb1 = (const float*)d_in[26];
    const float* outW = (const float*)d_in[27];
    const float* outb = (const float*)d_in[28];

    float* out      = (float*)d_out;
    float* attn_out = out + R_Q;  // preds first (B,T,N,1), then attn (B,T,NH,N,S)

    float *pQuery, *pQ, *pKV, *pCtx, *pComb, *pXln, *pGates, *pX1, *pX2;
    float *pHWh, *pG0, *pG1, *pWkv, *pBkv, *pWcc, *pBcc;
    cudaGetSymbolAddress((void**)&pQuery, g_query);
    cudaGetSymbolAddress((void**)&pQ,     g_Q);
    cudaGetSymbolAddress((void**)&pKV,    g_KV);
    cudaGetSymbolAddress((void**)&pCtx,   g_ctx);
    cudaGetSymbolAddress((void**)&pComb,  g_comb);
    cudaGetSymbolAddress((void**)&pXln,   g_xln);
    cudaGetSymbolAddress((void**)&pGates, g_gates);
    cudaGetSymbolAddress((void**)&pX1,    g_x1);
    cudaGetSymbolAddress((void**)&pX2,    g_x2);
    cudaGetSymbolAddress((void**)&pHWh,   g_hWh);
    cudaGetSymbolAddress((void**)&pG0,    g_G0);
    cudaGetSymbolAddress((void**)&pG1,    g_G1);
    cudaGetSymbolAddress((void**)&pWkv,   g_Wkv);
    cudaGetSymbolAddress((void**)&pBkv,   g_bkv);
    cudaGetSymbolAddress((void**)&pWcc,   g_Wcc);
    cudaGetSymbolAddress((void**)&pBcc,   g_bcc);

    // weight prep
    fuse_wkv_kernel<<<64, 512>>>(Wk, Wv, bk, bv);
    bcc_kernel<<<1, 128>>>(bo, ctxW, ctxb);
    sgemm_kernel<false><<<dim3(1, 1), 256>>>(Wo, ctxW + 128 * 128, pWcc, (const float*)nullptr, 128, 128);

    // query / projections
    build_query_kernel<<<(R_Q * Hd / 4 + 255) / 256, 256>>>(sq, h1);
    sgemm_kernel<false><<<dim3(1, 600), 256>>>(pQuery, Wq, pQ, bq, 128, 128);
    sgemm_kernel<false><<<dim3(2, 4200), 256>>>(enc, pWkv, pKV, pBkv, 128, 256);

    // attention (writes attn output + ctx)
    cudaFuncSetAttribute(attn_kernel, cudaFuncAttributeMaxDynamicSharedMemorySize, ATTN_SMEM);
    attn_kernel<<<dim3(Nd, Bd), 256, ATTN_SMEM>>>(pQ, pKV, attn_out, pCtx);

    // combined = query@ctx_W[:H] + ctx@(Wo@ctx_W[H:]) + (bo@ctx_W[H:] + ctx_b)
    sgemm_kernel<false><<<dim3(1, 600), 256>>>(pQuery, ctxW, pComb, pBcc, 128, 128);
    sgemm_kernel<true ><<<dim3(1, 600), 256>>>(pCtx, pWcc, pComb, (const float*)nullptr, 128, 128);

    // layer 0
    sgemm_kernel<false><<<dim3(4, 25), 256>>>(h0, Wh0, pHWh, (const float*)nullptr, 128, 512);
    agg_kernel<<<dim3(25, Bd), 512>>>(adj, pHWh, b0, pG0);
    ln_kernel<<<R_Q / 8, 256>>>(pComb, lng0, lnb0, pXln);
    sgemm_kernel<false><<<dim3(4, 600), 256>>>(pXln, Wx0, pGates, (const float*)nullptr, 128, 512);
    act_kernel<<<(R_Q * Hd + 255) / 256, 256>>>(pGates, pG0, c0, (const float*)nullptr, pX1);

    // layer 1 (+ residual)
    sgemm_kernel<false><<<dim3(4, 25), 256>>>(h1, Wh1, pHWh, (const float*)nullptr, 128, 512);
    agg_kernel<<<dim3(25, Bd), 512>>>(adj, pHWh, b1, pG1);
    ln_kernel<<<R_Q / 8, 256>>>(pX1, lng1, lnb1, pXln);
    sgemm_kernel<false><<<dim3(4, 600), 256>>>(pXln, Wx1, pGates, (const float*)nullptr, 128, 512);
    act_kernel<<<(R_Q * Hd + 255) / 256, 256>>>(pGates, pG1, c1, pX1, pX2);

    // preds
    preds_kernel<<<R_Q / 8, 256>>>(pX2, outW, outb, out);
}

// round 10
// speedup vs baseline: 1.4274x; 1.4274x over previous
#include <cuda_runtime.h>
#include <cuda_bf16.h>
#include <math.h>
#include <stdint.h>

#define Bd 16
#define Sd 168
#define Nd 200
#define Hd 128
#define Td 24
#define NHd 4
#define DHd 32

#define R_KV (Bd*Sd*Nd)      /* 537600 */
#define R_Q  (Bd*Td*Nd)      /* 76800  */

// ---------------- scratch (static device allocations; no cudaMalloc) ----------------
__device__ __nv_bfloat16 g_enc_h[(size_t)R_KV*Hd];
__device__ __nv_bfloat16 g_enc_l[(size_t)R_KV*Hd];
__device__ __nv_bfloat16 g_query_h[(size_t)R_Q*Hd];
__device__ __nv_bfloat16 g_query_l[(size_t)R_Q*Hd];
__device__ __nv_bfloat16 g_ctx_h[(size_t)R_Q*Hd];
__device__ __nv_bfloat16 g_ctx_l[(size_t)R_Q*Hd];
__device__ __nv_bfloat16 g_xln_h[(size_t)R_Q*Hd];
__device__ __nv_bfloat16 g_xln_l[(size_t)R_Q*Hd];
__device__ __nv_bfloat16 g_h0_h[3200*Hd], g_h0_l[3200*Hd];
__device__ __nv_bfloat16 g_h1_h[3200*Hd], g_h1_l[3200*Hd];
__device__ float g_Q[(size_t)R_Q*Hd];
__device__ float g_KV[(size_t)R_KV*256];   // K in cols 0..127, V in cols 128..255
__device__ float g_comb[(size_t)R_Q*Hd];
__device__ float g_gates[(size_t)R_Q*512];
__device__ float g_x1[(size_t)R_Q*Hd];
__device__ float g_x2[(size_t)R_Q*Hd];
__device__ float g_hWh[Bd*Nd*512];
__device__ float g_G0[Bd*Nd*512];
__device__ float g_G1[Bd*Nd*512];
// transposed/split weights [N,128] bf16 (k contiguous)
__device__ __nv_bfloat16 g_Wqt_h[128*128],  g_Wqt_l[128*128];
__device__ __nv_bfloat16 g_Wkvt_h[256*128], g_Wkvt_l[256*128];
__device__ __nv_bfloat16 g_Wtop_h[128*128], g_Wtop_l[128*128];
__device__ __nv_bfloat16 g_Wcct_h[128*128], g_Wcct_l[128*128];
__device__ __nv_bfloat16 g_Wx0t_h[512*128], g_Wx0t_l[512*128];
__device__ __nv_bfloat16 g_Wh0t_h[512*128], g_Wh0t_l[512*128];
__device__ __nv_bfloat16 g_Wx1t_h[512*128], g_Wx1t_l[512*128];
__device__ __nv_bfloat16 g_Wh1t_h[512*128], g_Wh1t_l[512*128];
__device__ float g_bkv[256];
__device__ float g_bcc[128];

// ---------------- helpers ----------------
__device__ __forceinline__ float sigmoidf_(float x) { return 1.f / (1.f + expf(-x)); }

__device__ __forceinline__ void store_split4(float4 v, __nv_bfloat16* hp, __nv_bfloat16* lp) {
    __nv_bfloat16 h0 = __float2bfloat16(v.x), h1 = __float2bfloat16(v.y),
                  h2 = __float2bfloat16(v.z), h3 = __float2bfloat16(v.w);
    __nv_bfloat16 l0 = __float2bfloat16(v.x - __bfloat162float(h0)),
                  l1 = __float2bfloat16(v.y - __bfloat162float(h1)),
                  l2 = __float2bfloat16(v.z - __bfloat162float(h2)),
                  l3 = __float2bfloat16(v.w - __bfloat162float(h3));
    __nv_bfloat162 a, b2, c, d;
    a.x = h0; a.y = h1; b2.x = h2; b2.y = h3;
    c.x = l0; c.y = l1; d.x  = l2; d.y  = l3;
    *(__nv_bfloat162*)hp       = a;
    *(__nv_bfloat162*)(hp + 2) = b2;
    *(__nv_bfloat162*)lp       = c;
    *(__nv_bfloat162*)(lp + 2) = d;
}

__device__ __forceinline__ uint32_t smem_u32(const void* p) {
    uint32_t a;
    asm("{ .reg .u64 t; cvta.to.shared.u64 t, %1; cvt.u32.u64 %0, t; }" : "=r"(a) : "l"(p));
    return a;
}

__device__ __forceinline__ void ldsm4(uint32_t* r, uint32_t addr) {
    asm volatile("ldmatrix.sync.aligned.m8n8.x4.shared.b16 {%0,%1,%2,%3}, [%4];"
        : "=r"(r[0]), "=r"(r[1]), "=r"(r[2]), "=r"(r[3]) : "r"(addr));
}

__device__ __forceinline__ void mma16816(float* c, const uint32_t* a, const uint32_t* b) {
    asm volatile("mma.sync.aligned.m16n8k16.row.col.f32.bf16.bf16.f32 "
        "{%0,%1,%2,%3}, {%4,%5,%6,%7}, {%8,%9}, {%0,%1,%2,%3};"
        : "+f"(c[0]), "+f"(c[1]), "+f"(c[2]), "+f"(c[3])
        : "r"(a[0]), "r"(a[1]), "r"(a[2]), "r"(a[3]), "r"(b[0]), "r"(b[1]));
}

// ---------------- bf16 split-precision MMA GEMM ----------------
// C[M x Nc] tile 128x128 = A[M x 128] @ Bt[Nc x 128]^T, 3 passes: AhBh + AhBl + AlBh.
// smem: 4 tiles of 128 rows x 136 bf16 (row stride 272B, ldmatrix conflict-free).
#define TSTRIDE 136
#define TILE_B  (128 * TSTRIDE * 2)     /* 34816 */
#define GEMM_SMEM (4 * TILE_B)          /* 139264 */

__device__ __forceinline__ void load_tile(char* dst, const __nv_bfloat16* __restrict__ src, int tid) {
    #pragma unroll
    for (int it = 0; it < 8; it++) {
        int c    = tid + it * 256;       // 2048 16B-chunks
        int row  = c >> 4;
        int col  = (c & 15) << 3;        // bf16 col
        uint4 v = *(const uint4*)(src + (size_t)row * 128 + col);
        *(uint4*)(dst + row * (TSTRIDE * 2) + col * 2) = v;
    }
}

__global__ void __launch_bounds__(256, 1)
gemm_mma_kernel(const __nv_bfloat16* __restrict__ Ah, const __nv_bfloat16* __restrict__ Al,
                const __nv_bfloat16* __restrict__ Bh, const __nv_bfloat16* __restrict__ Bl,
                float* __restrict__ C, const float* __restrict__ bias, int ldc, int accum)
{
    extern __shared__ __align__(16) char dynsm[];
    char* sAh = dynsm;
    char* sAl = dynsm + TILE_B;
    char* sBh = dynsm + 2 * TILE_B;
    char* sBl = dynsm + 3 * TILE_B;
    const int tid   = threadIdx.x;
    const int row0  = blockIdx.y * 128;
    const int col0  = blockIdx.x * 128;

    load_tile(sAh, Ah + (size_t)row0 * 128, tid);
    load_tile(sAl, Al + (size_t)row0 * 128, tid);
    load_tile(sBh, Bh + (size_t)col0 * 128, tid);
    load_tile(sBl, Bl + (size_t)col0 * 128, tid);
    __syncthreads();

    const int wid  = tid >> 5;
    const int lane = tid & 31;
    const int m0w  = (wid & 1) * 64;     // warp rows: 64
    const int n0w  = (wid >> 1) * 32;    // warp cols: 32

    // A fragment addresses: lanes 0-15 -> rows m+0..15 @ k0; lanes 16-31 -> same rows @ k0+8
    const uint32_t aOff = (uint32_t)((m0w + (lane & 15)) * TSTRIDE + (lane >> 4) * 8) * 2;
    uint32_t aH = smem_u32(sAh) + aOff;
    uint32_t aL = smem_u32(sAl) + aOff;
    // B fragment addresses (Bt[n][k]): group g=lane>>3: n_local=(g>>1)*8+(lane&7), k_local=(g&1)*8
    const int bg = lane >> 3;
    const uint32_t bOff = (uint32_t)((n0w + (bg >> 1) * 8 + (lane & 7)) * TSTRIDE + (bg & 1) * 8) * 2;
    uint32_t bH = smem_u32(sBh) + bOff;
    uint32_t bL = smem_u32(sBl) + bOff;

    float acc[4][4][4];
    #pragma unroll
    for (int mi = 0; mi < 4; mi++)
        #pragma unroll
        for (int ni = 0; ni < 4; ni++)
            #pragma unroll
            for (int q = 0; q < 4; q++) acc[mi][ni][q] = 0.f;

    #pragma unroll
    for (int kk = 0; kk < 8; kk++) {
        const uint32_t kb = kk * 32;     // 16 bf16 per k-step
        uint32_t ah[4][4], al[4][4], bh[2][4], bl[2][4];
        #pragma unroll
        for (int mi = 0; mi < 4; mi++) {
            ldsm4(ah[mi], aH + mi * (16 * TSTRIDE * 2) + kb);
            ldsm4(al[mi], aL + mi * (16 * TSTRIDE * 2) + kb);
        }
        #pragma unroll
        for (int pi = 0; pi < 2; pi++) {
            ldsm4(bh[pi], bH + pi * (16 * TSTRIDE * 2) + kb);
            ldsm4(bl[pi], bL + pi * (16 * TSTRIDE * 2) + kb);
        }
        #pragma unroll
        for (int mi = 0; mi < 4; mi++)
            #pragma unroll
            for (int ni = 0; ni < 4; ni++) {
                const uint32_t* bhf = &bh[ni >> 1][(ni & 1) * 2];
                const uint32_t* blf = &bl[ni >> 1][(ni & 1) * 2];
                mma16816(acc[mi][ni], ah[mi], bhf);   // hi*hi
                mma16816(acc[mi][ni], ah[mi], blf);   // hi*lo
                mma16816(acc[mi][ni], al[mi], bhf);   // lo*hi
            }
    }

    // epilogue: c0,c1 -> (row, col..col+1); c2,c3 -> (row+8, ...)
    const int mrow = lane >> 2;
    const int ncol = (lane & 3) * 2;
    #pragma unroll
    for (int mi = 0; mi < 4; mi++) {
        const int rg = row0 + m0w + mi * 16 + mrow;
        #pragma unroll
        for (int ni = 0; ni < 4; ni++) {
            const int cg = col0 + n0w + ni * 8 + ncol;
            float b0 = bias ? bias[cg] : 0.f;
            float b1 = bias ? bias[cg + 1] : 0.f;
            float* p0 = C + (size_t)rg * ldc + cg;
            float* p1 = C + (size_t)(rg + 8) * ldc + cg;
            float2 o0 = make_float2(acc[mi][ni][0] + b0, acc[mi][ni][1] + b1);
            float2 o1 = make_float2(acc[mi][ni][2] + b0, acc[mi][ni][3] + b1);
            if (accum) {
                float2 c0v = *(const float2*)p0;
                float2 c1v = *(const float2*)p1;
                o0.x += c0v.x; o0.y += c0v.y;
                o1.x += c1v.x; o1.y += c1v.y;
            }
            *(float2*)p0 = o0;
            *(float2*)p1 = o1;
        }
    }
}

// ---------------- weight prep ----------------
__global__ void wsplit_kernel(const float* __restrict__ W, int N,
                              __nv_bfloat16* __restrict__ th, __nv_bfloat16* __restrict__ tl) {
    int idx = blockIdx.x * blockDim.x + threadIdx.x;
    if (idx >= N * 128) return;
    int n = idx >> 7, k = idx & 127;
    float v = W[k * N + n];
    __nv_bfloat16 h = __float2bfloat16(v);
    th[idx] = h;
    tl[idx] = __float2bfloat16(v - __bfloat162float(h));
}

__global__ void wkvt_kernel(const float* __restrict__ Wk, const float* __restrict__ Wv,
                            const float* __restrict__ bk, const float* __restrict__ bv) {
    int idx = blockIdx.x * blockDim.x + threadIdx.x;  // 256*128
    if (idx < 256 * 128) {
        int n = idx >> 7, k = idx & 127;
        float v = (n < 128) ? Wk[k * 128 + n] : Wv[k * 128 + (n - 128)];
        __nv_bfloat16 h = __float2bfloat16(v);
        g_Wkvt_h[idx] = h;
        g_Wkvt_l[idx] = __float2bfloat16(v - __bfloat162float(h));
    }
    if (idx < 256) g_bkv[idx] = (idx < 128) ? bk[idx] : bv[idx - 128];
}

// Wcct[n,k] = sum_j Wo[k,j] * ctxW[128+j, n]  (= (Wo @ ctxW_bottom)^T), split to bf16
__global__ void wcct_kernel(const float* __restrict__ Wo, const float* __restrict__ ctxW) {
    int n = blockIdx.x, k = threadIdx.x;
    float s = 0.f;
    for (int j = 0; j < 128; j++) s += Wo[k * 128 + j] * ctxW[(128 + j) * 128 + n];
    __nv_bfloat16 h = __float2bfloat16(s);
    g_Wcct_h[n * 128 + k] = h;
    g_Wcct_l[n * 128 + k] = __float2bfloat16(s - __bfloat162float(h));
}

__global__ void bcc_kernel(const float* __restrict__ bo, const float* __restrict__ ctxW,
                           const float* __restrict__ ctxb) {
    int c = threadIdx.x;  // 128 threads
    float s = ctxb[c];
    for (int k = 0; k < 128; k++) s += bo[k] * ctxW[(128 + k) * 128 + c];
    g_bcc[c] = s;
}

__global__ void convert_split_kernel(const float* __restrict__ x,
                                     __nv_bfloat16* __restrict__ h, __nv_bfloat16* __restrict__ l,
                                     int n4) {
    int i = blockIdx.x * blockDim.x + threadIdx.x;
    if (i >= n4) return;
    float4 v = ((const float4*)x)[i];
    store_split4(v, h + (size_t)i * 4, l + (size_t)i * 4);
}

__global__ void build_query_kernel(const float* __restrict__ sq, const float* __restrict__ h1) {
    int i = blockIdx.x * blockDim.x + threadIdx.x;  // float4 index
    if (i >= R_Q * Hd / 4) return;
    int c4 = (i & 31) << 2;
    int r  = i >> 5;
    int t  = (r / Nd) % Td;
    int b  = r / (Td * Nd);
    int n  = r % Nd;
    float4 a  = *(const float4*)(sq + t * Hd + c4);
    float4 hh = *(const float4*)(h1 + ((size_t)(b * Nd + n)) * Hd + c4);
    float4 v  = make_float4(a.x + hh.x, a.y + hh.y, a.z + hh.z, a.w + hh.w);
    store_split4(v, g_query_h + (size_t)r * Hd + c4, g_query_l + (size_t)r * Hd + c4);
}

// ---------------- attention: one block per (b,n) ----------------
#define ATTN_SMEM ((24*132 + 168*132 + 96*168) * 4)

__global__ void __launch_bounds__(256) attn_kernel(
    const float* __restrict__ Q, const float* __restrict__ KV,
    float* __restrict__ attn_out,
    __nv_bfloat16* __restrict__ ctx_h, __nv_bfloat16* __restrict__ ctx_l)
{
    const int n = blockIdx.x;
    const int b = blockIdx.y;
    extern __shared__ __align__(16) char dynsm[];
    float* sm = (float*)dynsm;
    float* sQ = sm;               // 24*132
    float* sK = sm + 24*132;      // 168*132 (K then reused for V)
    float* sS = sK + 168*132;     // 96*168
    const int tid = threadIdx.x;

    {   // load Q rows for this (b,n)
        const float* qb = Q + ((size_t)(b * Td) * Nd + n) * Hd;
        for (int i = tid; i < Td * 32; i += 256) {
            int t = i >> 5, c4 = (i & 31) << 2;
            *(float4*)&sQ[t*132 + c4] = *(const float4*)(qb + (size_t)t * Nd * Hd + c4);
        }
    }
    {   // load K
        const float* kb = KV + ((size_t)(b * Sd) * Nd + n) * 256;
        for (int i = tid; i < Sd * 32; i += 256) {
            int s = i >> 5, c4 = (i & 31) << 2;
            *(float4*)&sK[s*132 + c4] = *(const float4*)(kb + (size_t)s * Nd * 256 + c4);
        }
    }
    __syncthreads();

    // ---- scores ----
    {
        const int hg  = tid >> 6;
        const int i_t = (tid >> 3) & 7;
        const int j_s = tid & 7;
        float acc[3][21];
        #pragma unroll
        for (int a = 0; a < 3; a++)
            #pragma unroll
            for (int c = 0; c < 21; c++) acc[a][c] = 0.f;
        #pragma unroll
        for (int d4 = 0; d4 < 8; d4++) {
            float4 q[3];
            #pragma unroll
            for (int a = 0; a < 3; a++)
                q[a] = *(const float4*)&sQ[(i_t + 8*a)*132 + hg*32 + d4*4];
            #pragma unroll
            for (int c = 0; c < 21; c++) {
                float4 k = *(const float4*)&sK[(j_s + 8*c)*132 + hg*32 + d4*4];
                #pragma unroll
                for (int a = 0; a < 3; a++)
                    acc[a][c] += q[a].x*k.x + q[a].y*k.y + q[a].z*k.z + q[a].w*k.w;
            }
        }
        const float scale = 0.17677669529663687f;  // 1/sqrt(32)
        #pragma unroll
        for (int a = 0; a < 3; a++)
            #pragma unroll
            for (int c = 0; c < 21; c++)
                sS[((i_t + 8*a)*4 + hg)*168 + (j_s + 8*c)] = acc[a][c] * scale;
    }
    __syncthreads();

    {   // load V into sK
        const float* vb = KV + ((size_t)(b * Sd) * Nd + n) * 256 + 128;
        for (int i = tid; i < Sd * 32; i += 256) {
            int s = i >> 5, c4 = (i & 31) << 2;
            *(float4*)&sK[s*132 + c4] = *(const float4*)(vb + (size_t)s * Nd * 256 + c4);
        }
    }

    // ---- softmax (writes attn output) ----
    {
        const int w = tid >> 5, lane = tid & 31;
        for (int rr = 0; rr < 12; rr++) {
            int row = w + (rr << 3);
            float* Sr = sS + row * 168;
            float vals[6];
            float vmax = -1e30f;
            #pragma unroll
            for (int k = 0; k < 6; k++) {
                int s = lane + (k << 5);
                vals[k] = (s < 168) ? Sr[s] : -1e30f;
                vmax = fmaxf(vmax, vals[k]);
            }
            #pragma unroll
            for (int o = 16; o > 0; o >>= 1) vmax = fmaxf(vmax, __shfl_xor_sync(~0u, vmax, o));
            float sum = 0.f;
            #pragma unroll
            for (int k = 0; k < 6; k++) {
                int s = lane + (k << 5);
                float e = (s < 168) ? expf(vals[k] - vmax) : 0.f;
                vals[k] = e; sum += e;
            }
            #pragma unroll
            for (int o = 16; o > 0; o >>= 1) sum += __shfl_xor_sync(~0u, sum, o);
            float inv = 1.f / sum;
            int t = row >> 2, h = row & 3;
            float* outp = attn_out + ((((size_t)(b * Td + t) * NHd + h) * Nd + n) * Sd);
            #pragma unroll
            for (int k = 0; k < 6; k++) {
                int s = lane + (k << 5);
                if (s < 168) { float p = vals[k] * inv; Sr[s] = p; outp[s] = p; }
            }
        }
    }
    __syncthreads();

    // ---- ctx = attn @ V (writes hi/lo bf16) ----
    {
        const int cq = tid & 31;
        const int tg = tid >> 5;
        const int c0 = cq << 2;
        const int h  = c0 >> 5;
        float acc2[3][4];
        #pragma unroll
        for (int a = 0; a < 3; a++)
            #pragma unroll
            for (int j = 0; j < 4; j++) acc2[a][j] = 0.f;
        #pragma unroll 4
        for (int s = 0; s < 168; s++) {
            float4 v = *(const float4*)&sK[s*132 + c0];
            #pragma unroll
            for (int a = 0; a < 3; a++) {
                int t = tg + (a << 3);
                float p = sS[(t*4 + h)*168 + s];
                acc2[a][0] += p * v.x; acc2[a][1] += p * v.y;
                acc2[a][2] += p * v.z; acc2[a][3] += p * v.w;
            }
        }
        #pragma unroll
        for (int a = 0; a < 3; a++) {
            int t = tg + (a << 3);
            size_t base = ((size_t)(b * Td + t) * Nd + n) * Hd + c0;
            float4 v = make_float4(acc2[a][0], acc2[a][1], acc2[a][2], acc2[a][3]);
            store_split4(v, ctx_h + base, ctx_l + base);
        }
    }
}

// ---------------- layernorm: one warp per 128-wide row; outputs bf16 hi/lo ----------------
__global__ void ln_kernel(const float* __restrict__ x, const float* __restrict__ g,
                          const float* __restrict__ bt,
                          __nv_bfloat16* __restrict__ yh, __nv_bfloat16* __restrict__ yl) {
    int w = threadIdx.x >> 5, lane = threadIdx.x & 31;
    int row = blockIdx.x * 8 + w;
    const float* xr = x + (size_t)row * 128;
    float4 v = *(const float4*)(xr + lane * 4);
    float s  = v.x + v.y + v.z + v.w;
    float sq = v.x*v.x + v.y*v.y + v.z*v.z + v.w*v.w;
    #pragma unroll
    for (int o = 16; o > 0; o >>= 1) {
        s  += __shfl_xor_sync(~0u, s,  o);
        sq += __shfl_xor_sync(~0u, sq, o);
    }
    float m   = s * (1.f / 128.f);
    float var = sq * (1.f / 128.f) - m * m;
    float inv = rsqrtf(var + 1e-5f);
    float4 gg = *(const float4*)(g + lane * 4);
    float4 bb = *(const float4*)(bt + lane * 4);
    float4 o4;
    o4.x = (v.x - m) * inv * gg.x + bb.x;
    o4.y = (v.y - m) * inv * gg.y + bb.y;
    o4.z = (v.z - m) * inv * gg.z + bb.z;
    o4.w = (v.w - m) * inv * gg.w + bb.w;
    store_split4(o4, yh + (size_t)row * 128 + lane * 4, yl + (size_t)row * 128 + lane * 4);
}

// ---------------- G[b,m,:] = sum_n adj[m,n]*hWh[b,n,:] + bias ----------------
__global__ void agg_kernel(const float* __restrict__ adj, const float* __restrict__ hWh,
                           const float* __restrict__ bv, float* __restrict__ G) {
    __shared__ float sA[8][200];
    int b = blockIdx.y, m0 = blockIdx.x * 8;
    int tid = threadIdx.x;  // 512
    for (int i = tid; i < 8 * 200; i += 512) {
        int m = i / 200, nn = i % 200;
        sA[m][nn] = adj[(m0 + m) * 200 + nn];
    }
    __syncthreads();
    int c = tid;
    float acc[8];
    #pragma unroll
    for (int m = 0; m < 8; m++) acc[m] = 0.f;
    const float* hb = hWh + (size_t)b * 200 * 512 + c;
    for (int nn = 0; nn < 200; nn++) {
        float v = hb[(size_t)nn * 512];
        #pragma unroll
        for (int m = 0; m < 8; m++) acc[m] += sA[m][nn] * v;
    }
    float bb = bv[c];
    #pragma unroll
    for (int m = 0; m < 8; m++)
        G[((size_t)b * 200 + m0 + m) * 512 + c] = acc[m] + bb;
}

// ---------------- fused LSTM activation ----------------
__global__ void act_kernel(const float* __restrict__ gates, const float* __restrict__ G,
                           const float* __restrict__ cin, const float* __restrict__ resid,
                           float* __restrict__ xout) {
    int idx = blockIdx.x * blockDim.x + threadIdx.x;
    if (idx >= R_Q * Hd) return;
    int h = idx & 127;
    int r = idx >> 7;
    int b = r / (Td * Nd);
    int n = r % Nd;
    size_t gb = ((size_t)(b * Nd) + n) * 512 + h;
    size_t gr = (size_t)r * 512 + h;
    float i_ = gates[gr]        + G[gb];
    float f_ = gates[gr + 128]  + G[gb + 128];
    float g_ = gates[gr + 256]  + G[gb + 256];
    float o_ = gates[gr + 384]  + G[gb + 384];
    float c  = cin[((size_t)(b * Nd) + n) * 128 + h];
    float cn = sigmoidf_(f_) * c + sigmoidf_(i_) * tanhf(g_);
    float x  = sigmoidf_(o_) * tanhf(cn);
    if (resid) x += resid[idx];
    xout[idx] = x;
}

// ---------------- preds ----------------
__global__ void preds_kernel(const float* __restrict__ x2, const float* __restrict__ W,
                             const float* __restrict__ ob, float* __restrict__ out) {
    int w = threadIdx.x >> 5, lane = threadIdx.x & 31;
    int r = blockIdx.x * 8 + w;
    float4 v  = *(const float4*)(x2 + (size_t)r * 128 + lane * 4);
    float4 ww = *(const float4*)(W + lane * 4);
    float s = v.x*ww.x + v.y*ww.y + v.z*ww.z + v.w*ww.w;
    #pragma unroll
    for (int o = 16; o > 0; o >>= 1) s += __shfl_xor_sync(~0u, s, o);
    if (lane == 0) out[r] = s + ob[0];
}

// ---------------- launch ----------------
#define GS(p, sym) cudaGetSymbolAddress((void**)&p, sym)

extern "C" void kernel_launch(void* const* d_in, const int* in_sizes, int n_in,
                              void* d_out, int out_size) {
    const float* enc  = (const float*)d_in[0];
    const float* h0   = (const float*)d_in[1];
    const float* c0   = (const float*)d_in[2];
    const float* h1   = (const float*)d_in[3];
    const float* c1   = (const float*)d_in[4];
    const float* adj  = (const float*)d_in[5];
    const float* sq   = (const float*)d_in[6];
    const float* Wq   = (const float*)d_in[7];
    const float* bq   = (const float*)d_in[8];
    const float* Wk   = (const float*)d_in[9];
    const float* bk   = (const float*)d_in[10];
    const float* Wv   = (const float*)d_in[11];
    const float* bv   = (const float*)d_in[12];
    const float* Wo   = (const float*)d_in[13];
    const float* bo   = (const float*)d_in[14];
    const float* ctxW = (const float*)d_in[15];
    const float* ctxb = (const float*)d_in[16];
    const float* Wx0  = (const float*)d_in[17];
    const float* Wh0  = (const float*)d_in[18];
    const float* b0   = (const float*)d_in[19];
    const float* lng0 = (const float*)d_in[20];
    const float* lnb0 = (const float*)d_in[21];
    const float* Wx1  = (const float*)d_in[22];
    const float* Wh1  = (const float*)d_in[23];
    const float* b1   = (const float*)d_in[24];
    const float* lng1 = (const float*)d_in[25];
    const float* lnb1 = (const float*)d_in[26];
    const float* outW = (const float*)d_in[27];
    const float* outb = (const float*)d_in[28];

    float* out      = (float*)d_out;
    float* attn_out = out + R_Q;  // preds (B,T,N,1) then attn (B,T,NH,N,S)

    __nv_bfloat16 *pEh, *pEl, *pQh, *pQl, *pCh, *pCl, *pXh, *pXl;
    __nv_bfloat16 *pH0h, *pH0l, *pH1h, *pH1l;
    __nv_bfloat16 *pWqh, *pWql, *pWkvh, *pWkvl, *pWth, *pWtl, *pWcch, *pWccl;
    __nv_bfloat16 *pWx0h, *pWx0l, *pWh0h, *pWh0l, *pWx1h, *pWx1l, *pWh1h, *pWh1l;
    float *pQf, *pKV, *pComb, *pGates, *pX1, *pX2, *pHWh, *pG0, *pG1, *pBkv, *pBcc;
    GS(pEh, g_enc_h);   GS(pEl, g_enc_l);
    GS(pQh, g_query_h); GS(pQl, g_query_l);
    GS(pCh, g_ctx_h);   GS(pCl, g_ctx_l);
    GS(pXh, g_xln_h);   GS(pXl, g_xln_l);
    GS(pH0h, g_h0_h);   GS(pH0l, g_h0_l);
    GS(pH1h, g_h1_h);   GS(pH1l, g_h1_l);
    GS(pWqh, g_Wqt_h);  GS(pWql, g_Wqt_l);
    GS(pWkvh, g_Wkvt_h); GS(pWkvl, g_Wkvt_l);
    GS(pWth, g_Wtop_h); GS(pWtl, g_Wtop_l);
    GS(pWcch, g_Wcct_h); GS(pWccl, g_Wcct_l);
    GS(pWx0h, g_Wx0t_h); GS(pWx0l, g_Wx0t_l);
    GS(pWh0h, g_Wh0t_h); GS(pWh0l, g_Wh0t_l);
    GS(pWx1h, g_Wx1t_h); GS(pWx1l, g_Wx1t_l);
    GS(pWh1h, g_Wh1t_h); GS(pWh1l, g_Wh1t_l);
    GS(pQf, g_Q);       GS(pKV, g_KV);
    GS(pComb, g_comb);  GS(pGates, g_gates);
    GS(pX1, g_x1);      GS(pX2, g_x2);
    GS(pHWh, g_hWh);    GS(pG0, g_G0);    GS(pG1, g_G1);
    GS(pBkv, g_bkv);    GS(pBcc, g_bcc);

    cudaFuncSetAttribute(gemm_mma_kernel, cudaFuncAttributeMaxDynamicSharedMemorySize, GEMM_SMEM);
    cudaFuncSetAttribute(attn_kernel,     cudaFuncAttributeMaxDynamicSharedMemorySize, ATTN_SMEM);

    // --- weight prep ---
    wkvt_kernel<<<128, 256>>>(Wk, Wv, bk, bv);
    wsplit_kernel<<<64, 256>>>(Wq, 128, pWqh, pWql);
    wsplit_kernel<<<64, 256>>>(ctxW, 128, pWth, pWtl);   // top half of ctx_W
    wcct_kernel<<<128, 128>>>(Wo, ctxW);
    bcc_kernel<<<1, 128>>>(bo, ctxW, ctxb);
    wsplit_kernel<<<256, 256>>>(Wx0, 512, pWx0h, pWx0l);
    wsplit_kernel<<<256, 256>>>(Wh0, 512, pWh0h, pWh0l);
    wsplit_kernel<<<256, 256>>>(Wx1, 512, pWx1h, pWx1l);
    wsplit_kernel<<<256, 256>>>(Wh1, 512, pWh1h, pWh1l);

    // --- activation conversions ---
    convert_split_kernel<<<(R_KV * 32 + 255) / 256, 256>>>(enc, pEh, pEl, R_KV * 32);
    convert_split_kernel<<<400, 256>>>(h0, pH0h, pH0l, 3200 * 32);
    convert_split_kernel<<<400, 256>>>(h1, pH1h, pH1l, 3200 * 32);
    build_query_kernel<<<(R_Q * 32 + 255) / 256, 256>>>(sq, h1);

    // --- projections (mma) ---
    gemm_mma_kernel<<<dim3(1, 600), 256, GEMM_SMEM>>>(pQh, pQl, pWqh, pWql, pQf, bq, 128, 0);
    gemm_mma_kernel<<<dim3(2, 4200), 256, GEMM_SMEM>>>(pEh, pEl, pWkvh, pWkvl, pKV, pBkv, 256, 0);

    // --- attention ---
    attn_kernel<<<dim3(Nd, Bd), 256, ATTN_SMEM>>>(pQf, pKV, attn_out, pCh, pCl);

    // --- combined = query@ctxW_top + ctx@Wcc + bcc ---
    gemm_mma_kernel<<<dim3(1, 600), 256, GEMM_SMEM>>>(pQh, pQl, pWth, pWtl, pComb, pBcc, 128, 0);
    gemm_mma_kernel<<<dim3(1, 600), 256, GEMM_SMEM>>>(pCh, pCl, pWcch, pWccl, pComb, (const float*)0, 128, 1);

    // --- layer 0 ---
    gemm_mma_kernel<<<dim3(4, 25), 256, GEMM_SMEM>>>(pH0h, pH0l, pWh0h, pWh0l, pHWh, (const float*)0, 512, 0);
    agg_kernel<<<dim3(25, Bd), 512>>>(adj, pHWh, b0, pG0);
    ln_kernel<<<R_Q / 8, 256>>>(pComb, lng0, lnb0, pXh, pXl);
    gemm_mma_kernel<<<dim3(4, 600), 256, GEMM_SMEM>>>(pXh, pXl, pWx0h, pWx0l, pGates, (const float*)0, 512, 0);
    act_kernel<<<(R_Q * Hd + 255) / 256, 256>>>(pGates, pG0, c0, (const float*)0, pX1);

    // --- layer 1 (+ residual) ---
    gemm_mma_kernel<<<dim3(4, 25), 256, GEMM_SMEM>>>(pH1h, pH1l, pWh1h, pWh1l, pHWh, (const float*)0, 512, 0);
    agg_kernel<<<dim3(25, Bd), 512>>>(adj, pHWh, b1, pG1);
    ln_kernel<<<R_Q / 8, 256>>>(pX1, lng1, lnb1, pXh, pXl);
    gemm_mma_kernel<<<dim3(4, 600), 256, GEMM_SMEM>>>(pXh, pXl, pWx1h, pWx1l, pGates, (const float*)0, 512, 0);
    act_kernel<<<(R_Q * Hd + 255) / 256, 256>>>(pGates, pG1, c1, pX1, pX2);

    // --- preds ---
    preds_kernel<<<R_Q / 8, 256>>>(pX2, outW, outb, out);
}

// round 14
// speedup vs baseline: 1.5497x; 1.0856x over previous
#include <cuda_runtime.h>
#include <cuda_bf16.h>
#include <math.h>
#include <stdint.h>

#define Bd 16
#define Sd 168
#define Nd 200
#define Hd 128
#define Td 24
#define NHd 4
#define DHd 32

#define R_KV (Bd*Sd*Nd)      /* 537600 */
#define R_Q  (Bd*Td*Nd)      /* 76800  */

// ---------------- scratch (static device allocations; no cudaMalloc) ----------------
__device__ __nv_bfloat16 g_enc_h[(size_t)R_KV*Hd];
__device__ __nv_bfloat16 g_enc_l[(size_t)R_KV*Hd];
__device__ __nv_bfloat16 g_query_h[(size_t)R_Q*Hd];
__device__ __nv_bfloat16 g_query_l[(size_t)R_Q*Hd];
__device__ __nv_bfloat16 g_ctx_h[(size_t)R_Q*Hd];
__device__ __nv_bfloat16 g_ctx_l[(size_t)R_Q*Hd];
__device__ __nv_bfloat16 g_xln_h[(size_t)R_Q*Hd];
__device__ __nv_bfloat16 g_xln_l[(size_t)R_Q*Hd];
__device__ __nv_bfloat16 g_h0_h[3200*Hd], g_h0_l[3200*Hd];
__device__ __nv_bfloat16 g_h1_h[3200*Hd], g_h1_l[3200*Hd];
__device__ float g_Q[(size_t)R_Q*Hd];
__device__ float g_KV[(size_t)R_KV*256];   // K in cols 0..127, V in cols 128..255
__device__ float g_comb[(size_t)R_Q*Hd];
__device__ float g_gates[(size_t)R_Q*512];
__device__ float g_x1[(size_t)R_Q*Hd];
__device__ float g_x2[(size_t)R_Q*Hd];
__device__ float g_hWh[Bd*Nd*512];
__device__ float g_G0[Bd*Nd*512];
__device__ float g_G1[Bd*Nd*512];
// transposed/split weights [N,128] bf16 (k contiguous)
__device__ __nv_bfloat16 g_Wqt_h[128*128],  g_Wqt_l[128*128];
__device__ __nv_bfloat16 g_Wkvt_h[256*128], g_Wkvt_l[256*128];
__device__ __nv_bfloat16 g_Wtop_h[128*128], g_Wtop_l[128*128];
__device__ __nv_bfloat16 g_Wcct_h[128*128], g_Wcct_l[128*128];
__device__ __nv_bfloat16 g_Wx0t_h[512*128], g_Wx0t_l[512*128];
__device__ __nv_bfloat16 g_Wh0t_h[512*128], g_Wh0t_l[512*128];
__device__ __nv_bfloat16 g_Wx1t_h[512*128], g_Wx1t_l[512*128];
__device__ __nv_bfloat16 g_Wh1t_h[512*128], g_Wh1t_l[512*128];
__device__ float g_bkv[256];
__device__ float g_bcc[128];

// ---------------- helpers ----------------
__device__ __forceinline__ float sigmoidf_(float x) { return 1.f / (1.f + expf(-x)); }

__device__ __forceinline__ void store_split4(float4 v, __nv_bfloat16* hp, __nv_bfloat16* lp) {
    __nv_bfloat16 h0 = __float2bfloat16(v.x), h1 = __float2bfloat16(v.y),
                  h2 = __float2bfloat16(v.z), h3 = __float2bfloat16(v.w);
    __nv_bfloat16 l0 = __float2bfloat16(v.x - __bfloat162float(h0)),
                  l1 = __float2bfloat16(v.y - __bfloat162float(h1)),
                  l2 = __float2bfloat16(v.z - __bfloat162float(h2)),
                  l3 = __float2bfloat16(v.w - __bfloat162float(h3));
    __nv_bfloat162 a, b2, c, d;
    a.x = h0; a.y = h1; b2.x = h2; b2.y = h3;
    c.x = l0; c.y = l1; d.x  = l2; d.y  = l3;
    *(__nv_bfloat162*)hp       = a;
    *(__nv_bfloat162*)(hp + 2) = b2;
    *(__nv_bfloat162*)lp       = c;
    *(__nv_bfloat162*)(lp + 2) = d;
}

__device__ __forceinline__ uint32_t smem_u32(const void* p) {
    uint32_t a;
    asm("{ .reg .u64 t; cvta.to.shared.u64 t, %1; cvt.u32.u64 %0, t; }" : "=r"(a) : "l"(p));
    return a;
}

__device__ __forceinline__ void ldsm4(uint32_t* r, uint32_t addr) {
    asm volatile("ldmatrix.sync.aligned.m8n8.x4.shared.b16 {%0,%1,%2,%3}, [%4];"
        : "=r"(r[0]), "=r"(r[1]), "=r"(r[2]), "=r"(r[3]) : "r"(addr));
}

__device__ __forceinline__ void mma16816(float* c, const uint32_t* a, const uint32_t* b) {
    asm volatile("mma.sync.aligned.m16n8k16.row.col.f32.bf16.bf16.f32 "
        "{%0,%1,%2,%3}, {%4,%5,%6,%7}, {%8,%9}, {%0,%1,%2,%3};"
        : "+f"(c[0]), "+f"(c[1]), "+f"(c[2]), "+f"(c[3])
        : "r"(a[0]), "r"(a[1]), "r"(a[2]), "r"(a[3]), "r"(b[0]), "r"(b[1]));
}

__device__ __forceinline__ void cpa16(uint32_t d, const void* s) {
    asm volatile("cp.async.cg.shared.global [%0], [%1], 16;" :: "r"(d), "l"(s));
}

// ---------------- pipelined bf16 split-precision MMA GEMM ----------------
// C tile 128x128 = A[Mx128] @ Bt[Nc x 128]^T, 3 passes: AhBh + AhBl + AlBh.
// K=128 fixed, BK=32 chunks, 2-stage cp.async double buffer, 2 CTAs/SM.
#define TS   40                         /* row stride in bf16 */
#define TSB  (TS*2)                     /* 80 bytes */
#define TILE_STAGE (128*TSB)            /* 10240 B per tile per stage */
#define STAGE_B (4*TILE_STAGE)          /* 40960 B per stage */
#define GEMM_SMEM (2*STAGE_B)           /* 81920 B */

__device__ __forceinline__ void gemm_issue(uint32_t sb, int buf, int kt,
        const __nv_bfloat16* a0, const __nv_bfloat16* a1,
        const __nv_bfloat16* b0, const __nv_bfloat16* b1, int tid) {
    const __nv_bfloat16* s[4] = {a0, a1, b0, b1};
    uint32_t dst = sb + buf * STAGE_B;
    #pragma unroll
    for (int t4 = 0; t4 < 4; t4++) {
        #pragma unroll
        for (int rep = 0; rep < 2; rep++) {
            int c   = tid + rep * 256;        // 0..511 16B-chunks per tile
            int row = c >> 2, seg = c & 3;
            cpa16(dst + t4 * TILE_STAGE + row * TSB + seg * 16,
                  s[t4] + (size_t)row * 128 + kt * 32 + seg * 8);
        }
    }
    asm volatile("cp.async.commit_group;" ::: "memory");
}

__global__ void __launch_bounds__(256, 2)
gemm_mma_kernel(const __nv_bfloat16* __restrict__ Ah, const __nv_bfloat16* __restrict__ Al,
                const __nv_bfloat16* __restrict__ Bh, const __nv_bfloat16* __restrict__ Bl,
                float* __restrict__ C, const float* __restrict__ bias, int ldc, int accum)
{
    extern __shared__ __align__(16) char dynsm[];
    const uint32_t sb = smem_u32(dynsm);
    const int tid  = threadIdx.x;
    const int row0 = blockIdx.y * 128;
    const int col0 = blockIdx.x * 128;

    const __nv_bfloat16* a0 = Ah + (size_t)row0 * 128;
    const __nv_bfloat16* a1 = Al + (size_t)row0 * 128;
    const __nv_bfloat16* b0 = Bh + (size_t)col0 * 128;
    const __nv_bfloat16* b1 = Bl + (size_t)col0 * 128;

    const int wid  = tid >> 5;
    const int lane = tid & 31;
    const int m0w  = (wid & 1) * 64;
    const int n0w  = (wid >> 1) * 32;

    const uint32_t aOff = (uint32_t)((m0w + (lane & 15)) * TS + (lane >> 4) * 8) * 2;
    const int bg = lane >> 3;
    const uint32_t bOff = (uint32_t)((n0w + (bg >> 1) * 8 + (lane & 7)) * TS + (bg & 1) * 8) * 2;

    float acc[4][4][4];
    #pragma unroll
    for (int mi = 0; mi < 4; mi++)
        #pragma unroll
        for (int ni = 0; ni < 4; ni++)
            #pragma unroll
            for (int q = 0; q < 4; q++) acc[mi][ni][q] = 0.f;

    gemm_issue(sb, 0, 0, a0, a1, b0, b1, tid);

    #pragma unroll
    for (int kt = 0; kt < 4; kt++) {
        if (kt < 3) {
            gemm_issue(sb, (kt + 1) & 1, kt + 1, a0, a1, b0, b1, tid);
            asm volatile("cp.async.wait_group 1;" ::: "memory");
        } else {
            asm volatile("cp.async.wait_group 0;" ::: "memory");
        }
        __syncthreads();

        const uint32_t base = sb + (kt & 1) * STAGE_B;
        const uint32_t aHb = base + aOff;
        const uint32_t aLb = base + TILE_STAGE + aOff;
        const uint32_t bHb = base + 2 * TILE_STAGE + bOff;
        const uint32_t bLb = base + 3 * TILE_STAGE + bOff;

        #pragma unroll
        for (int kk = 0; kk < 2; kk++) {
            const uint32_t kb = kk * 32;   // 16 bf16 = 32B
            uint32_t ah[4][4], bh[2][4], bl[2][4];
            #pragma unroll
            for (int mi = 0; mi < 4; mi++) ldsm4(ah[mi], aHb + mi * (16 * TSB) + kb);
            #pragma unroll
            for (int pi = 0; pi < 2; pi++) ldsm4(bh[pi], bHb + pi * (16 * TSB) + kb);
            #pragma unroll
            for (int pi = 0; pi < 2; pi++) ldsm4(bl[pi], bLb + pi * (16 * TSB) + kb);
            #pragma unroll
            for (int mi = 0; mi < 4; mi++)
                #pragma unroll
                for (int ni = 0; ni < 4; ni++) {
                    const uint32_t* bhf = &bh[ni >> 1][(ni & 1) * 2];
                    const uint32_t* blf = &bl[ni >> 1][(ni & 1) * 2];
                    mma16816(acc[mi][ni], ah[mi], bhf);   // hi*hi
                    mma16816(acc[mi][ni], ah[mi], blf);   // hi*lo
                }
            #pragma unroll
            for (int mi = 0; mi < 4; mi++) {
                uint32_t alt[4];
                ldsm4(alt, aLb + mi * (16 * TSB) + kb);
                #pragma unroll
                for (int ni = 0; ni < 4; ni++)
                    mma16816(acc[mi][ni], alt, &bh[ni >> 1][(ni & 1) * 2]);  // lo*hi
            }
        }
        __syncthreads();
    }

    // epilogue: c0,c1 -> (row, col..col+1); c2,c3 -> (row+8, ...)
    const int mrow = lane >> 2;
    const int ncol = (lane & 3) * 2;
    #pragma unroll
    for (int mi = 0; mi < 4; mi++) {
        const int rg = row0 + m0w + mi * 16 + mrow;
        #pragma unroll
        for (int ni = 0; ni < 4; ni++) {
            const int cg = col0 + n0w + ni * 8 + ncol;
            float b0v = bias ? bias[cg] : 0.f;
            float b1v = bias ? bias[cg + 1] : 0.f;
            float* p0 = C + (size_t)rg * ldc + cg;
            float* p1 = C + (size_t)(rg + 8) * ldc + cg;
            float2 o0 = make_float2(acc[mi][ni][0] + b0v, acc[mi][ni][1] + b1v);
            float2 o1 = make_float2(acc[mi][ni][2] + b0v, acc[mi][ni][3] + b1v);
            if (accum) {
                float2 c0v = *(const float2*)p0;
                float2 c1v = *(const float2*)p1;
                o0.x += c0v.x; o0.y += c0v.y;
                o1.x += c1v.x; o1.y += c1v.y;
            }
            *(float2*)p0 = o0;
            *(float2*)p1 = o1;
        }
    }
}

// ---------------- weight prep ----------------
// W[K=128][N] -> th/tl[N][128] via 32x32 smem tile transpose (coalesced both sides).
// grid (N/32, 4), block (32, 8)
__global__ void wsplit_kernel(const float* __restrict__ W, int N,
                              __nv_bfloat16* __restrict__ th, __nv_bfloat16* __restrict__ tl) {
    __shared__ float t[32][33];
    int nb = blockIdx.x * 32, kb = blockIdx.y * 32;
    int tx = threadIdx.x, ty = threadIdx.y;
    #pragma unroll
    for (int i = 0; i < 32; i += 8)
        t[ty + i][tx] = W[(size_t)(kb + ty + i) * N + nb + tx];
    __syncthreads();
    #pragma unroll
    for (int i = 0; i < 32; i += 8) {
        int n = nb + ty + i, k = kb + tx;
        float v = t[tx][ty + i];
        __nv_bfloat16 h = __float2bfloat16(v);
        th[n * 128 + k] = h;
        tl[n * 128 + k] = __float2bfloat16(v - __bfloat162float(h));
    }
}

__global__ void bkv_kernel(const float* __restrict__ bk, const float* __restrict__ bv) {
    int i = threadIdx.x;  // 256
    g_bkv[i] = (i < 128) ? bk[i] : bv[i - 128];
}

// Wcct[n,k] = sum_j Wo[k,j] * ctxW[128+j, n]; block=k (uniform Wo), thread=n (coalesced ctxW)
__global__ void wcct_kernel(const float* __restrict__ Wo, const float* __restrict__ ctxW) {
    int k = blockIdx.x, n = threadIdx.x;  // 128 x 128
    float s = 0.f;
    #pragma unroll 4
    for (int j = 0; j < 128; j++)
        s += Wo[k * 128 + j] * ctxW[(128 + j) * 128 + n];
    __nv_bfloat16 h = __float2bfloat16(s);
    g_Wcct_h[n * 128 + k] = h;
    g_Wcct_l[n * 128 + k] = __float2bfloat16(s - __bfloat162float(h));
}

__global__ void bcc_kernel(const float* __restrict__ bo, const float* __restrict__ ctxW,
                           const float* __restrict__ ctxb) {
    int c = threadIdx.x;  // 128 threads
    float s = ctxb[c];
    for (int k = 0; k < 128; k++) s += bo[k] * ctxW[(128 + k) * 128 + c];
    g_bcc[c] = s;
}

__global__ void convert_split_kernel(const float* __restrict__ x,
                                     __nv_bfloat16* __restrict__ h, __nv_bfloat16* __restrict__ l,
                                     int n4) {
    int i = blockIdx.x * blockDim.x + threadIdx.x;
    if (i >= n4) return;
    float4 v = ((const float4*)x)[i];
    store_split4(v, h + (size_t)i * 4, l + (size_t)i * 4);
}

__global__ void build_query_kernel(const float* __restrict__ sq, const float* __restrict__ h1) {
    int i = blockIdx.x * blockDim.x + threadIdx.x;  // float4 index
    if (i >= R_Q * Hd / 4) return;
    int c4 = (i & 31) << 2;
    int r  = i >> 5;
    int t  = (r / Nd) % Td;
    int b  = r / (Td * Nd);
    int n  = r % Nd;
    float4 a  = *(const float4*)(sq + t * Hd + c4);
    float4 hh = *(const float4*)(h1 + ((size_t)(b * Nd + n)) * Hd + c4);
    float4 v  = make_float4(a.x + hh.x, a.y + hh.y, a.z + hh.z, a.w + hh.w);
    store_split4(v, g_query_h + (size_t)r * Hd + c4, g_query_l + (size_t)r * Hd + c4);
}

// ---------------- attention: one block per (b,n) ----------------
#define ATTN_SMEM ((24*132 + 168*132 + 96*168) * 4)

__global__ void __launch_bounds__(256) attn_kernel(
    const float* __restrict__ Q, const float* __restrict__ KV,
    float* __restrict__ attn_out,
    __nv_bfloat16* __restrict__ ctx_h, __nv_bfloat16* __restrict__ ctx_l)
{
    const int n = blockIdx.x;
    const int b = blockIdx.y;
    extern __shared__ __align__(16) char dynsm[];
    float* sm = (float*)dynsm;
    float* sQ = sm;               // 24*132
    float* sK = sm + 24*132;      // 168*132 (K then reused for V)
    float* sS = sK + 168*132;     // 96*168
    const int tid = threadIdx.x;

    {   // load Q rows for this (b,n)
        const float* qb = Q + ((size_t)(b * Td) * Nd + n) * Hd;
        for (int i = tid; i < Td * 32; i += 256) {
            int t = i >> 5, c4 = (i & 31) << 2;
            *(float4*)&sQ[t*132 + c4] = *(const float4*)(qb + (size_t)t * Nd * Hd + c4);
        }
    }
    {   // load K
        const float* kb = KV + ((size_t)(b * Sd) * Nd + n) * 256;
        for (int i = tid; i < Sd * 32; i += 256) {
            int s = i >> 5, c4 = (i & 31) << 2;
            *(float4*)&sK[s*132 + c4] = *(const float4*)(kb + (size_t)s * Nd * 256 + c4);
        }
    }
    __syncthreads();

    // ---- scores ----
    {
        const int hg  = tid >> 6;
        const int i_t = (tid >> 3) & 7;
        const int j_s = tid & 7;
        float acc[3][21];
        #pragma unroll
        for (int a = 0; a < 3; a++)
            #pragma unroll
            for (int c = 0; c < 21; c++) acc[a][c] = 0.f;
        #pragma unroll
        for (int d4 = 0; d4 < 8; d4++) {
            float4 q[3];
            #pragma unroll
            for (int a = 0; a < 3; a++)
                q[a] = *(const float4*)&sQ[(i_t + 8*a)*132 + hg*32 + d4*4];
            #pragma unroll
            for (int c = 0; c < 21; c++) {
                float4 k = *(const float4*)&sK[(j_s + 8*c)*132 + hg*32 + d4*4];
                #pragma unroll
                for (int a = 0; a < 3; a++)
                    acc[a][c] += q[a].x*k.x + q[a].y*k.y + q[a].z*k.z + q[a].w*k.w;
            }
        }
        const float scale = 0.17677669529663687f;  // 1/sqrt(32)
        #pragma unroll
        for (int a = 0; a < 3; a++)
            #pragma unroll
            for (int c = 0; c < 21; c++)
                sS[((i_t + 8*a)*4 + hg)*168 + (j_s + 8*c)] = acc[a][c] * scale;
    }
    __syncthreads();

    {   // load V into sK
        const float* vb = KV + ((size_t)(b * Sd) * Nd + n) * 256 + 128;
        for (int i = tid; i < Sd * 32; i += 256) {
            int s = i >> 5, c4 = (i & 31) << 2;
            *(float4*)&sK[s*132 + c4] = *(const float4*)(vb + (size_t)s * Nd * 256 + c4);
        }
    }

    // ---- softmax (writes attn output) ----
    {
        const int w = tid >> 5, lane = tid & 31;
        for (int rr = 0; rr < 12; rr++) {
            int row = w + (rr << 3);
            float* Sr = sS + row * 168;
            float vals[6];
            float vmax = -1e30f;
            #pragma unroll
            for (int k = 0; k < 6; k++) {
                int s = lane + (k << 5);
                vals[k] = (s < 168) ? Sr[s] : -1e30f;
                vmax = fmaxf(vmax, vals[k]);
            }
            #pragma unroll
            for (int o = 16; o > 0; o >>= 1) vmax = fmaxf(vmax, __shfl_xor_sync(~0u, vmax, o));
            float sum = 0.f;
            #pragma unroll
            for (int k = 0; k < 6; k++) {
                int s = lane + (k << 5);
                float e = (s < 168) ? expf(vals[k] - vmax) : 0.f;
                vals[k] = e; sum += e;
            }
            #pragma unroll
            for (int o = 16; o > 0; o >>= 1) sum += __shfl_xor_sync(~0u, sum, o);
            float inv = 1.f / sum;
            int t = row >> 2, h = row & 3;
            float* outp = attn_out + ((((size_t)(b * Td + t) * NHd + h) * Nd + n) * Sd);
            #pragma unroll
            for (int k = 0; k < 6; k++) {
                int s = lane + (k << 5);
                if (s < 168) { float p = vals[k] * inv; Sr[s] = p; outp[s] = p; }
            }
        }
    }
    __syncthreads();

    // ---- ctx = attn @ V (writes hi/lo bf16) ----
    {
        const int cq = tid & 31;
        const int tg = tid >> 5;
        const int c0 = cq << 2;
        const int h  = c0 >> 5;
        float acc2[3][4];
        #pragma unroll
        for (int a = 0; a < 3; a++)
            #pragma unroll
            for (int j = 0; j < 4; j++) acc2[a][j] = 0.f;
        #pragma unroll 4
        for (int s = 0; s < 168; s++) {
            float4 v = *(const float4*)&sK[s*132 + c0];
            #pragma unroll
            for (int a = 0; a < 3; a++) {
                int t = tg + (a << 3);
                float p = sS[(t*4 + h)*168 + s];
                acc2[a][0] += p * v.x; acc2[a][1] += p * v.y;
                acc2[a][2] += p * v.z; acc2[a][3] += p * v.w;
            }
        }
        #pragma unroll
        for (int a = 0; a < 3; a++) {
            int t = tg + (a << 3);
            size_t base = ((size_t)(b * Td + t) * Nd + n) * Hd + c0;
            float4 v = make_float4(acc2[a][0], acc2[a][1], acc2[a][2], acc2[a][3]);
            store_split4(v, ctx_h + base, ctx_l + base);
        }
    }
}

// ---------------- layernorm: one warp per 128-wide row; outputs bf16 hi/lo ----------------
__global__ void ln_kernel(const float* __restrict__ x, const float* __restrict__ g,
                          const float* __restrict__ bt,
                          __nv_bfloat16* __restrict__ yh, __nv_bfloat16* __restrict__ yl) {
    int w = threadIdx.x >> 5, lane = threadIdx.x & 31;
    int row = blockIdx.x * 8 + w;
    const float* xr = x + (size_t)row * 128;
    float4 v = *(const float4*)(xr + lane * 4);
    float s  = v.x + v.y + v.z + v.w;
    float sq = v.x*v.x + v.y*v.y + v.z*v.z + v.w*v.w;
    #pragma unroll
    for (int o = 16; o > 0; o >>= 1) {
        s  += __shfl_xor_sync(~0u, s,  o);
        sq += __shfl_xor_sync(~0u, sq, o);
    }
    float m   = s * (1.f / 128.f);
    float var = sq * (1.f / 128.f) - m * m;
    float inv = rsqrtf(var + 1e-5f);
    float4 gg = *(const float4*)(g + lane * 4);
    float4 bb = *(const float4*)(bt + lane * 4);
    float4 o4;
    o4.x = (v.x - m) * inv * gg.x + bb.x;
    o4.y = (v.y - m) * inv * gg.y + bb.y;
    o4.z = (v.z - m) * inv * gg.z + bb.z;
    o4.w = (v.w - m) * inv * gg.w + bb.w;
    store_split4(o4, yh + (size_t)row * 128 + lane * 4, yl + (size_t)row * 128 + lane * 4);
}

// ---------------- G[b,m,:] = sum_n adj[m,n]*hWh[b,n,:] + bias ----------------
__global__ void agg_kernel(const float* __restrict__ adj, const float* __restrict__ hWh,
                           const float* __restrict__ bv, float* __restrict__ G) {
    __shared__ float sA[8][200];
    int b = blockIdx.y, m0 = blockIdx.x * 8;
    int tid = threadIdx.x;  // 512
    for (int i = tid; i < 8 * 200; i += 512) {
        int m = i / 200, nn = i % 200;
        sA[m][nn] = adj[(m0 + m) * 200 + nn];
    }
    __syncthreads();
    int c = tid;
    float acc[8];
    #pragma unroll
    for (int m = 0; m < 8; m++) acc[m] = 0.f;
    const float* hb = hWh + (size_t)b * 200 * 512 + c;
    for (int nn = 0; nn < 200; nn++) {
        float v = hb[(size_t)nn * 512];
        #pragma unroll
        for (int m = 0; m < 8; m++) acc[m] += sA[m][nn] * v;
    }
    float bb = bv[c];
    #pragma unroll
    for (int m = 0; m < 8; m++)
        G[((size_t)b * 200 + m0 + m) * 512 + c] = acc[m] + bb;
}

// ---------------- fused LSTM activation ----------------
__global__ void act_kernel(const float* __restrict__ gates, const float* __restrict__ G,
                           const float* __restrict__ cin, const float* __restrict__ resid,
                           float* __restrict__ xout) {
    int idx = blockIdx.x * blockDim.x + threadIdx.x;
    if (idx >= R_Q * Hd) return;
    int h = idx & 127;
    int r = idx >> 7;
    int b = r / (Td * Nd);
    int n = r % Nd;
    size_t gb = ((size_t)(b * Nd) + n) * 512 + h;
    size_t gr = (size_t)r * 512 + h;
    float i_ = gates[gr]        + G[gb];
    float f_ = gates[gr + 128]  + G[gb + 128];
    float g_ = gates[gr + 256]  + G[gb + 256];
    float o_ = gates[gr + 384]  + G[gb + 384];
    float c  = cin[((size_t)(b * Nd) + n) * 128 + h];
    float cn = sigmoidf_(f_) * c + sigmoidf_(i_) * tanhf(g_);
    float x  = sigmoidf_(o_) * tanhf(cn);
    if (resid) x += resid[idx];
    xout[idx] = x;
}

// ---------------- preds ----------------
__global__ void preds_kernel(const float* __restrict__ x2, const float* __restrict__ W,
                             const float* __restrict__ ob, float* __restrict__ out) {
    int w = threadIdx.x >> 5, lane = threadIdx.x & 31;
    int r = blockIdx.x * 8 + w;
    float4 v  = *(const float4*)(x2 + (size_t)r * 128 + lane * 4);
    float4 ww = *(const float4*)(W + lane * 4);
    float s = v.x*ww.x + v.y*ww.y + v.z*ww.z + v.w*ww.w;
    #pragma unroll
    for (int o = 16; o > 0; o >>= 1) s += __shfl_xor_sync(~0u, s, o);
    if (lane == 0) out[r] = s + ob[0];
}

// ---------------- launch ----------------
#define GS(p, sym) cudaGetSymbolAddress((void**)&p, sym)

extern "C" void kernel_launch(void* const* d_in, const int* in_sizes, int n_in,
                              void* d_out, int out_size) {
    const float* enc  = (const float*)d_in[0];
    const float* h0   = (const float*)d_in[1];
    const float* c0   = (const float*)d_in[2];
    const float* h1   = (const float*)d_in[3];
    const float* c1   = (const float*)d_in[4];
    const float* adj  = (const float*)d_in[5];
    const float* sq   = (const float*)d_in[6];
    const float* Wq   = (const float*)d_in[7];
    const float* bq   = (const float*)d_in[8];
    const float* Wk   = (const float*)d_in[9];
    const float* bk   = (const float*)d_in[10];
    const float* Wv   = (const float*)d_in[11];
    const float* bv   = (const float*)d_in[12];
    const float* Wo   = (const float*)d_in[13];
    const float* bo   = (const float*)d_in[14];
    const float* ctxW = (const float*)d_in[15];
    const float* ctxb = (const float*)d_in[16];
    const float* Wx0  = (const float*)d_in[17];
    const float* Wh0  = (const float*)d_in[18];
    const float* b0   = (const float*)d_in[19];
    const float* lng0 = (const float*)d_in[20];
    const float* lnb0 = (const float*)d_in[21];
    const float* Wx1  = (const float*)d_in[22];
    const float* Wh1  = (const float*)d_in[23];
    const float* b1   = (const float*)d_in[24];
    const float* lng1 = (const float*)d_in[25];
    const float* lnb1 = (const float*)d_in[26];
    const float* outW = (const float*)d_in[27];
    const float* outb = (const float*)d_in[28];

    float* out      = (float*)d_out;
    float* attn_out = out + R_Q;  // preds (B,T,N,1) then attn (B,T,NH,N,S)

    __nv_bfloat16 *pEh, *pEl, *pQh, *pQl, *pCh, *pCl, *pXh, *pXl;
    __nv_bfloat16 *pH0h, *pH0l, *pH1h, *pH1l;
    __nv_bfloat16 *pWqh, *pWql, *pWkvh, *pWkvl, *pWth, *pWtl, *pWcch, *pWccl;
    __nv_bfloat16 *pWx0h, *pWx0l, *pWh0h, *pWh0l, *pWx1h, *pWx1l, *pWh1h, *pWh1l;
    float *pQf, *pKV, *pComb, *pGates, *pX1, *pX2, *pHWh, *pG0, *pG1, *pBkv, *pBcc;
    GS(pEh, g_enc_h);   GS(pEl, g_enc_l);
    GS(pQh, g_query_h); GS(pQl, g_query_l);
    GS(pCh, g_ctx_h);   GS(pCl, g_ctx_l);
    GS(pXh, g_xln_h);   GS(pXl, g_xln_l);
    GS(pH0h, g_h0_h);   GS(pH0l, g_h0_l);
    GS(pH1h, g_h1_h);   GS(pH1l, g_h1_l);
    GS(pWqh, g_Wqt_h);  GS(pWql, g_Wqt_l);
    GS(pWkvh, g_Wkvt_h); GS(pWkvl, g_Wkvt_l);
    GS(pWth, g_Wtop_h); GS(pWtl, g_Wtop_l);
    GS(pWcch, g_Wcct_h); GS(pWccl, g_Wcct_l);
    GS(pWx0h, g_Wx0t_h); GS(pWx0l, g_Wx0t_l);
    GS(pWh0h, g_Wh0t_h); GS(pWh0l, g_Wh0t_l);
    GS(pWx1h, g_Wx1t_h); GS(pWx1l, g_Wx1t_l);
    GS(pWh1h, g_Wh1t_h); GS(pWh1l, g_Wh1t_l);
    GS(pQf, g_Q);       GS(pKV, g_KV);
    GS(pComb, g_comb);  GS(pGates, g_gates);
    GS(pX1, g_x1);      GS(pX2, g_x2);
    GS(pHWh, g_hWh);    GS(pG0, g_G0);    GS(pG1, g_G1);
    GS(pBkv, g_bkv);    GS(pBcc, g_bcc);

    cudaFuncSetAttribute(gemm_mma_kernel, cudaFuncAttributeMaxDynamicSharedMemorySize, GEMM_SMEM);
    cudaFuncSetAttribute(attn_kernel,     cudaFuncAttributeMaxDynamicSharedMemorySize, ATTN_SMEM);

    // --- weight prep (tiled transpose + split) ---
    wsplit_kernel<<<dim3(4, 4),  dim3(32, 8)>>>(Wk, 128, pWkvh, pWkvl);
    wsplit_kernel<<<dim3(4, 4),  dim3(32, 8)>>>(Wv, 128, pWkvh + 128*128, pWkvl + 128*128);
    bkv_kernel<<<1, 256>>>(bk, bv);
    wsplit_kernel<<<dim3(4, 4),  dim3(32, 8)>>>(Wq, 128, pWqh, pWql);
    wsplit_kernel<<<dim3(4, 4),  dim3(32, 8)>>>(ctxW, 128, pWth, pWtl);   // top half of ctx_W
    wcct_kernel<<<128, 128>>>(Wo, ctxW);
    bcc_kernel<<<1, 128>>>(bo, ctxW, ctxb);
    wsplit_kernel<<<dim3(16, 4), dim3(32, 8)>>>(Wx0, 512, pWx0h, pWx0l);
    wsplit_kernel<<<dim3(16, 4), dim3(32, 8)>>>(Wh0, 512, pWh0h, pWh0l);
    wsplit_kernel<<<dim3(16, 4), dim3(32, 8)>>>(Wx1, 512, pWx1h, pWx1l);
    wsplit_kernel<<<dim3(16, 4), dim3(32, 8)>>>(Wh1, 512, pWh1h, pWh1l);

    // --- activation conversions ---
    convert_split_kernel<<<(R_KV * 32 + 255) / 256, 256>>>(enc, pEh, pEl, R_KV * 32);
    convert_split_kernel<<<400, 256>>>(h0, pH0h, pH0l, 3200 * 32);
    convert_split_kernel<<<400, 256>>>(h1, pH1h, pH1l, 3200 * 32);
    build_query_kernel<<<(R_Q * 32 + 255) / 256, 256>>>(sq, h1);

    // --- projections (mma) ---
    gemm_mma_kernel<<<dim3(1, 600), 256, GEMM_SMEM>>>(pQh, pQl, pWqh, pWql, pQf, bq, 128, 0);
    gemm_mma_kernel<<<dim3(2, 4200), 256, GEMM_SMEM>>>(pEh, pEl, pWkvh, pWkvl, pKV, pBkv, 256, 0);

    // --- attention ---
    attn_kernel<<<dim3(Nd, Bd), 256, ATTN_SMEM>>>(pQf, pKV, attn_out, pCh, pCl);

    // --- combined = query@ctxW_top + ctx@Wcc + bcc ---
    gemm_mma_kernel<<<dim3(1, 600), 256, GEMM_SMEM>>>(pQh, pQl, pWth, pWtl, pComb, pBcc, 128, 0);
    gemm_mma_kernel<<<dim3(1, 600), 256, GEMM_SMEM>>>(pCh, pCl, pWcch, pWccl, pComb, (const float*)0, 128, 1);

    // --- layer 0 ---
    gemm_mma_kernel<<<dim3(4, 25), 256, GEMM_SMEM>>>(pH0h, pH0l, pWh0h, pWh0l, pHWh, (const float*)0, 512, 0);
    agg_kernel<<<dim3(25, Bd), 512>>>(adj, pHWh, b0, pG0);
    ln_kernel<<<R_Q / 8, 256>>>(pComb, lng0, lnb0, pXh, pXl);
    gemm_mma_kernel<<<dim3(4, 600), 256, GEMM_SMEM>>>(pXh, pXl, pWx0h, pWx0l, pGates, (const float*)0, 512, 0);
    act_kernel<<<(R_Q * Hd + 255) / 256, 256>>>(pGates, pG0, c0, (const float*)0, pX1);

    // --- layer 1 (+ residual) ---
    gemm_mma_kernel<<<dim3(4, 25), 256, GEMM_SMEM>>>(pH1h, pH1l, pWh1h, pWh1l, pHWh, (const float*)0, 512, 0);
    agg_kernel<<<dim3(25, Bd), 512>>>(adj, pHWh, b1, pG1);
    ln_kernel<<<R_Q / 8, 256>>>(pX1, lng1, lnb1, pXh, pXl);
    gemm_mma_kernel<<<dim3(4, 600), 256, GEMM_SMEM>>>(pXh, pXl, pWx1h, pWx1l, pGates, (const float*)0, 512, 0);
    act_kernel<<<(R_Q * Hd + 255) / 256, 256>>>(pGates, pG1, c1, pX1, pX2);

    // --- preds ---
    preds_kernel<<<R_Q / 8, 256>>>(pX2, outW, outb, out);
}

// round 15
// speedup vs baseline: 1.6223x; 1.0468x over previous
#include <cuda_runtime.h>
#include <cuda_bf16.h>
#include <math.h>
#include <stdint.h>

#define Bd 16
#define Sd 168
#define Nd 200
#define Hd 128
#define Td 24
#define NHd 4
#define DHd 32

#define R_KV (Bd*Sd*Nd)      /* 537600 */
#define R_Q  (Bd*Td*Nd)      /* 76800  */

// ---------------- scratch (static device allocations; no cudaMalloc) ----------------
__device__ __nv_bfloat16 g_query_h[(size_t)R_Q*Hd];
__device__ __nv_bfloat16 g_query_l[(size_t)R_Q*Hd];
__device__ __nv_bfloat16 g_ctx_h[(size_t)R_Q*Hd];
__device__ __nv_bfloat16 g_ctx_l[(size_t)R_Q*Hd];
__device__ __nv_bfloat16 g_xln_h[(size_t)R_Q*Hd];
__device__ __nv_bfloat16 g_xln_l[(size_t)R_Q*Hd];
__device__ __nv_bfloat16 g_h0_h[3200*Hd], g_h0_l[3200*Hd];
__device__ __nv_bfloat16 g_h1_h[3200*Hd], g_h1_l[3200*Hd];
__device__ float g_Q[(size_t)R_Q*Hd];
__device__ float g_KV[(size_t)R_KV*256];   // K in cols 0..127, V in cols 128..255
__device__ float g_comb[(size_t)R_Q*Hd];
__device__ float g_gates[(size_t)R_Q*512];
__device__ float g_x1[(size_t)R_Q*Hd];
__device__ float g_hWh[Bd*Nd*512];
__device__ float g_G0[Bd*Nd*512];
__device__ float g_G1[Bd*Nd*512];
// transposed/split weights [N,128] bf16 (k contiguous)
__device__ __nv_bfloat16 g_Wqt_h[128*128],  g_Wqt_l[128*128];
__device__ __nv_bfloat16 g_Wkvt_h[256*128], g_Wkvt_l[256*128];
__device__ __nv_bfloat16 g_Wtop_h[128*128], g_Wtop_l[128*128];
__device__ __nv_bfloat16 g_Wcct_h[128*128], g_Wcct_l[128*128];
__device__ __nv_bfloat16 g_Wx0t_h[512*128], g_Wx0t_l[512*128];
__device__ __nv_bfloat16 g_Wh0t_h[512*128], g_Wh0t_l[512*128];
__device__ __nv_bfloat16 g_Wx1t_h[512*128], g_Wx1t_l[512*128];
__device__ __nv_bfloat16 g_Wh1t_h[512*128], g_Wh1t_l[512*128];
__device__ float g_bkv[256];
__device__ float g_bcc[128];

// ---------------- helpers ----------------
__device__ __forceinline__ float sigmoidf_(float x) { return 1.f / (1.f + expf(-x)); }

__device__ __forceinline__ void store_split4(float4 v, __nv_bfloat16* hp, __nv_bfloat16* lp) {
    __nv_bfloat16 h0 = __float2bfloat16(v.x), h1 = __float2bfloat16(v.y),
                  h2 = __float2bfloat16(v.z), h3 = __float2bfloat16(v.w);
    __nv_bfloat16 l0 = __float2bfloat16(v.x - __bfloat162float(h0)),
                  l1 = __float2bfloat16(v.y - __bfloat162float(h1)),
                  l2 = __float2bfloat16(v.z - __bfloat162float(h2)),
                  l3 = __float2bfloat16(v.w - __bfloat162float(h3));
    __nv_bfloat162 a, b2, c, d;
    a.x = h0; a.y = h1; b2.x = h2; b2.y = h3;
    c.x = l0; c.y = l1; d.x  = l2; d.y  = l3;
    *(__nv_bfloat162*)hp       = a;
    *(__nv_bfloat162*)(hp + 2) = b2;
    *(__nv_bfloat162*)lp       = c;
    *(__nv_bfloat162*)(lp + 2) = d;
}

__device__ __forceinline__ uint32_t smem_u32(const void* p) {
    uint32_t a;
    asm("{ .reg .u64 t; cvta.to.shared.u64 t, %1; cvt.u32.u64 %0, t; }" : "=r"(a) : "l"(p));
    return a;
}

__device__ __forceinline__ void ldsm4(uint32_t* r, uint32_t addr) {
    asm volatile("ldmatrix.sync.aligned.m8n8.x4.shared.b16 {%0,%1,%2,%3}, [%4];"
        : "=r"(r[0]), "=r"(r[1]), "=r"(r[2]), "=r"(r[3]) : "r"(addr));
}

__device__ __forceinline__ void mma16816(float* c, const uint32_t* a, const uint32_t* b) {
    asm volatile("mma.sync.aligned.m16n8k16.row.col.f32.bf16.bf16.f32 "
        "{%0,%1,%2,%3}, {%4,%5,%6,%7}, {%8,%9}, {%0,%1,%2,%3};"
        : "+f"(c[0]), "+f"(c[1]), "+f"(c[2]), "+f"(c[3])
        : "r"(a[0]), "r"(a[1]), "r"(a[2]), "r"(a[3]), "r"(b[0]), "r"(b[1]));
}

__device__ __forceinline__ void cpa16(uint32_t d, const void* s) {
    asm volatile("cp.async.cg.shared.global [%0], [%1], 16;" :: "r"(d), "l"(s));
}

// ---------------- pipelined bf16 split-precision MMA GEMM (generic, 128x128 tile) ----------------
#define TS   40                         /* row stride in bf16 */
#define TSB  (TS*2)                     /* 80 bytes */
#define TILE_STAGE (128*TSB)            /* 10240 B per tile per stage */
#define STAGE_B (4*TILE_STAGE)          /* 40960 B per stage */
#define GEMM_SMEM (2*STAGE_B)           /* 81920 B */

__device__ __forceinline__ void gemm_issue(uint32_t sb, int buf, int kt,
        const __nv_bfloat16* a0, const __nv_bfloat16* a1,
        const __nv_bfloat16* b0, const __nv_bfloat16* b1, int tid) {
    const __nv_bfloat16* s[4] = {a0, a1, b0, b1};
    uint32_t dst = sb + buf * STAGE_B;
    #pragma unroll
    for (int t4 = 0; t4 < 4; t4++) {
        #pragma unroll
        for (int rep = 0; rep < 2; rep++) {
            int c   = tid + rep * 256;        // 0..511 16B-chunks per tile
            int row = c >> 2, seg = c & 3;
            cpa16(dst + t4 * TILE_STAGE + row * TSB + seg * 16,
                  s[t4] + (size_t)row * 128 + kt * 32 + seg * 8);
        }
    }
    asm volatile("cp.async.commit_group;" ::: "memory");
}

__global__ void __launch_bounds__(256, 2)
gemm_mma_kernel(const __nv_bfloat16* __restrict__ Ah, const __nv_bfloat16* __restrict__ Al,
                const __nv_bfloat16* __restrict__ Bh, const __nv_bfloat16* __restrict__ Bl,
                float* __restrict__ C, const float* __restrict__ bias, int ldc, int accum)
{
    extern __shared__ __align__(16) char dynsm[];
    const uint32_t sb = smem_u32(dynsm);
    const int tid  = threadIdx.x;
    const int row0 = blockIdx.y * 128;
    const int col0 = blockIdx.x * 128;

    const __nv_bfloat16* a0 = Ah + (size_t)row0 * 128;
    const __nv_bfloat16* a1 = Al + (size_t)row0 * 128;
    const __nv_bfloat16* b0 = Bh + (size_t)col0 * 128;
    const __nv_bfloat16* b1 = Bl + (size_t)col0 * 128;

    const int wid  = tid >> 5;
    const int lane = tid & 31;
    const int m0w  = (wid & 1) * 64;
    const int n0w  = (wid >> 1) * 32;

    const uint32_t aOff = (uint32_t)((m0w + (lane & 15)) * TS + (lane >> 4) * 8) * 2;
    const int bg = lane >> 3;
    const uint32_t bOff = (uint32_t)((n0w + (bg >> 1) * 8 + (lane & 7)) * TS + (bg & 1) * 8) * 2;

    float acc[4][4][4];
    #pragma unroll
    for (int mi = 0; mi < 4; mi++)
        #pragma unroll
        for (int ni = 0; ni < 4; ni++)
            #pragma unroll
            for (int q = 0; q < 4; q++) acc[mi][ni][q] = 0.f;

    gemm_issue(sb, 0, 0, a0, a1, b0, b1, tid);

    #pragma unroll
    for (int kt = 0; kt < 4; kt++) {
        if (kt < 3) {
            gemm_issue(sb, (kt + 1) & 1, kt + 1, a0, a1, b0, b1, tid);
            asm volatile("cp.async.wait_group 1;" ::: "memory");
        } else {
            asm volatile("cp.async.wait_group 0;" ::: "memory");
        }
        __syncthreads();

        const uint32_t base = sb + (kt & 1) * STAGE_B;
        const uint32_t aHb = base + aOff;
        const uint32_t aLb = base + TILE_STAGE + aOff;
        const uint32_t bHb = base + 2 * TILE_STAGE + bOff;
        const uint32_t bLb = base + 3 * TILE_STAGE + bOff;

        #pragma unroll
        for (int kk = 0; kk < 2; kk++) {
            const uint32_t kb = kk * 32;   // 16 bf16 = 32B
            uint32_t ah[4][4], bh[2][4], bl[2][4];
            #pragma unroll
            for (int mi = 0; mi < 4; mi++) ldsm4(ah[mi], aHb + mi * (16 * TSB) + kb);
            #pragma unroll
            for (int pi = 0; pi < 2; pi++) ldsm4(bh[pi], bHb + pi * (16 * TSB) + kb);
            #pragma unroll
            for (int pi = 0; pi < 2; pi++) ldsm4(bl[pi], bLb + pi * (16 * TSB) + kb);
            #pragma unroll
            for (int mi = 0; mi < 4; mi++)
                #pragma unroll
                for (int ni = 0; ni < 4; ni++) {
                    const uint32_t* bhf = &bh[ni >> 1][(ni & 1) * 2];
                    const uint32_t* blf = &bl[ni >> 1][(ni & 1) * 2];
                    mma16816(acc[mi][ni], ah[mi], bhf);   // hi*hi
                    mma16816(acc[mi][ni], ah[mi], blf);   // hi*lo
                }
            #pragma unroll
            for (int mi = 0; mi < 4; mi++) {
                uint32_t alt[4];
                ldsm4(alt, aLb + mi * (16 * TSB) + kb);
                #pragma unroll
                for (int ni = 0; ni < 4; ni++)
                    mma16816(acc[mi][ni], alt, &bh[ni >> 1][(ni & 1) * 2]);  // lo*hi
            }
        }
        __syncthreads();
    }

    const int mrow = lane >> 2;
    const int ncol = (lane & 3) * 2;
    #pragma unroll
    for (int mi = 0; mi < 4; mi++) {
        const int rg = row0 + m0w + mi * 16 + mrow;
        #pragma unroll
        for (int ni = 0; ni < 4; ni++) {
            const int cg = col0 + n0w + ni * 8 + ncol;
            float b0v = bias ? bias[cg] : 0.f;
            float b1v = bias ? bias[cg + 1] : 0.f;
            float* p0 = C + (size_t)rg * ldc + cg;
            float* p1 = C + (size_t)(rg + 8) * ldc + cg;
            float2 o0 = make_float2(acc[mi][ni][0] + b0v, acc[mi][ni][1] + b1v);
            float2 o1 = make_float2(acc[mi][ni][2] + b0v, acc[mi][ni][3] + b1v);
            if (accum) {
                float2 c0v = *(const float2*)p0;
                float2 c1v = *(const float2*)p1;
                o0.x += c0v.x; o0.y += c0v.y;
                o1.x += c1v.x; o1.y += c1v.y;
            }
            *(float2*)p0 = o0;
            *(float2*)p1 = o1;
        }
    }
}

// ---------------- fused KV GEMM: C[128 x 256] = enc_fp32 @ Wkv^T, A split in registers ----------------
#define KV_ATILE (128*TSB)              /* 10240 */
#define KV_BTILE (256*TSB)              /* 20480 */
#define KV_STAGE (2*KV_ATILE + 2*KV_BTILE)  /* 61440 */
#define KV_SMEM  (2*KV_STAGE)           /* 122880 */

__device__ __forceinline__ void kv_issueB(uint32_t sb, int buf, int kt,
        const __nv_bfloat16* b0, const __nv_bfloat16* b1, int tid) {
    uint32_t dst = sb + buf * KV_STAGE + 2 * KV_ATILE;
    #pragma unroll
    for (int t4 = 0; t4 < 2; t4++) {
        const __nv_bfloat16* src = t4 ? b1 : b0;
        #pragma unroll
        for (int rep = 0; rep < 4; rep++) {
            int c = tid + rep * 256;          // 0..1023 chunks (256 rows x 4)
            int row = c >> 2, seg = c & 3;
            cpa16(dst + t4 * KV_BTILE + row * TSB + seg * 16,
                  src + (size_t)row * 128 + kt * 32 + seg * 8);
        }
    }
    asm volatile("cp.async.commit_group;" ::: "memory");
}

__device__ __forceinline__ void kv_loadA(float4* ar, const float* aP, int kt, int tid) {
    #pragma unroll
    for (int rep = 0; rep < 2; rep++) {
        int c = tid + rep * 256;              // 0..511 chunks of 8 floats
        int row = c >> 2, seg = c & 3;
        const float* p = aP + (size_t)row * 128 + kt * 32 + seg * 8;
        ar[rep * 2 + 0] = *(const float4*)p;
        ar[rep * 2 + 1] = *(const float4*)(p + 4);
    }
}

__device__ __forceinline__ void kv_stsA(uint32_t sb, int buf, const float4* ar, int tid) {
    uint32_t dh = sb + buf * KV_STAGE;
    uint32_t dl = dh + KV_ATILE;
    #pragma unroll
    for (int rep = 0; rep < 2; rep++) {
        int c = tid + rep * 256;
        int row = c >> 2, seg = c & 3;
        __nv_bfloat16 hb[8], lb[8];
        const float* f = (const float*)&ar[rep * 2];
        #pragma unroll
        for (int j = 0; j < 8; j++) {
            hb[j] = __float2bfloat16(f[j]);
            lb[j] = __float2bfloat16(f[j] - __bfloat162float(hb[j]));
        }
        uint32_t off = row * TSB + seg * 16;
        asm volatile("st.shared.v4.b32 [%0], {%1,%2,%3,%4};" :: "r"(dh + off),
            "r"(*(const uint32_t*)&hb[0]), "r"(*(const uint32_t*)&hb[2]),
            "r"(*(const uint32_t*)&hb[4]), "r"(*(const uint32_t*)&hb[6]));
        asm volatile("st.shared.v4.b32 [%0], {%1,%2,%3,%4};" :: "r"(dl + off),
            "r"(*(const uint32_t*)&lb[0]), "r"(*(const uint32_t*)&lb[2]),
            "r"(*(const uint32_t*)&lb[4]), "r"(*(const uint32_t*)&lb[6]));
    }
}

__global__ void __launch_bounds__(256, 1)
gemm_kv_kernel(const float* __restrict__ A,
               const __nv_bfloat16* __restrict__ Bh, const __nv_bfloat16* __restrict__ Bl,
               float* __restrict__ C, const float* __restrict__ bias)
{
    extern __shared__ __align__(16) char dynsm[];
    const uint32_t sb = smem_u32(dynsm);
    const int tid  = threadIdx.x;
    const int row0 = blockIdx.x * 128;
    const float* aP = A + (size_t)row0 * 128;

    const int wid  = tid >> 5;
    const int lane = tid & 31;
    const int m0w  = (wid & 1) * 64;
    const int n0w  = (wid >> 1) * 64;

    const uint32_t aOff = (uint32_t)((m0w + (lane & 15)) * TS + (lane >> 4) * 8) * 2;
    const int bg = lane >> 3;
    const uint32_t bOff = (uint32_t)((n0w + (bg >> 1) * 8 + (lane & 7)) * TS + (bg & 1) * 8) * 2;

    float acc[4][8][4];
    #pragma unroll
    for (int mi = 0; mi < 4; mi++)
        #pragma unroll
        for (int ni = 0; ni < 8; ni++)
            #pragma unroll
            for (int q = 0; q < 4; q++) acc[mi][ni][q] = 0.f;

    float4 ar[4];
    kv_loadA(ar, aP, 0, tid);
    kv_issueB(sb, 0, 0, Bh, Bl, tid);
    kv_stsA(sb, 0, ar, tid);
    kv_loadA(ar, aP, 1, tid);
    kv_issueB(sb, 1, 1, Bh, Bl, tid);

    #pragma unroll
    for (int kt = 0; kt < 4; kt++) {
        if (kt < 3) asm volatile("cp.async.wait_group 1;" ::: "memory");
        else        asm volatile("cp.async.wait_group 0;" ::: "memory");
        __syncthreads();

        const uint32_t base = sb + (kt & 1) * KV_STAGE;
        const uint32_t aHb = base + aOff;
        const uint32_t aLb = base + KV_ATILE + aOff;
        const uint32_t bHb = base + 2 * KV_ATILE + bOff;
        const uint32_t bLb = base + 2 * KV_ATILE + KV_BTILE + bOff;

        #pragma unroll
        for (int kk = 0; kk < 2; kk++) {
            const uint32_t kb = kk * 32;
            uint32_t ah[4][4], bh[4][4], bl[4][4];
            #pragma unroll
            for (int mi = 0; mi < 4; mi++) ldsm4(ah[mi], aHb + mi * (16 * TSB) + kb);
            #pragma unroll
            for (int pi = 0; pi < 4; pi++) ldsm4(bh[pi], bHb + pi * (16 * TSB) + kb);
            #pragma unroll
            for (int pi = 0; pi < 4; pi++) ldsm4(bl[pi], bLb + pi * (16 * TSB) + kb);
            #pragma unroll
            for (int mi = 0; mi < 4; mi++)
                #pragma unroll
                for (int ni = 0; ni < 8; ni++) {
                    const uint32_t* bhf = &bh[ni >> 1][(ni & 1) * 2];
                    const uint32_t* blf = &bl[ni >> 1][(ni & 1) * 2];
                    mma16816(acc[mi][ni], ah[mi], bhf);
                    mma16816(acc[mi][ni], ah[mi], blf);
                }
            #pragma unroll
            for (int mi = 0; mi < 4; mi++) {
                uint32_t alt[4];
                ldsm4(alt, aLb + mi * (16 * TSB) + kb);
                #pragma unroll
                for (int ni = 0; ni < 8; ni++)
                    mma16816(acc[mi][ni], alt, &bh[ni >> 1][(ni & 1) * 2]);
            }
        }
        __syncthreads();

        if (kt < 3) {
            kv_stsA(sb, (kt + 1) & 1, ar, tid);
            if (kt < 2) {
                kv_loadA(ar, aP, kt + 2, tid);
                kv_issueB(sb, kt & 1, kt + 2, Bh, Bl, tid);
            }
        }
    }

    const int mrow = lane >> 2;
    const int ncol = (lane & 3) * 2;
    #pragma unroll
    for (int mi = 0; mi < 4; mi++) {
        const int rg = row0 + m0w + mi * 16 + mrow;
        #pragma unroll
        for (int ni = 0; ni < 8; ni++) {
            const int cg = n0w + ni * 8 + ncol;
            float b0v = bias[cg], b1v = bias[cg + 1];
            float* p0 = C + (size_t)rg * 256 + cg;
            float* p1 = C + (size_t)(rg + 8) * 256 + cg;
            *(float2*)p0 = make_float2(acc[mi][ni][0] + b0v, acc[mi][ni][1] + b1v);
            *(float2*)p1 = make_float2(acc[mi][ni][2] + b0v, acc[mi][ni][3] + b1v);
        }
    }
}

// ---------------- weight prep ----------------
__global__ void wsplit_kernel(const float* __restrict__ W, int N,
                              __nv_bfloat16* __restrict__ th, __nv_bfloat16* __restrict__ tl) {
    __shared__ float t[32][33];
    int nb = blockIdx.x * 32, kb = blockIdx.y * 32;
    int tx = threadIdx.x, ty = threadIdx.y;
    #pragma unroll
    for (int i = 0; i < 32; i += 8)
        t[ty + i][tx] = W[(size_t)(kb + ty + i) * N + nb + tx];
    __syncthreads();
    #pragma unroll
    for (int i = 0; i < 32; i += 8) {
        int n = nb + ty + i, k = kb + tx;
        float v = t[tx][ty + i];
        __nv_bfloat16 h = __float2bfloat16(v);
        th[n * 128 + k] = h;
        tl[n * 128 + k] = __float2bfloat16(v - __bfloat162float(h));
    }
}

__global__ void bkv_kernel(const float* __restrict__ bk, const float* __restrict__ bv) {
    int i = threadIdx.x;
    g_bkv[i] = (i < 128) ? bk[i] : bv[i - 128];
}

__global__ void wcct_kernel(const float* __restrict__ Wo, const float* __restrict__ ctxW) {
    int k = blockIdx.x, n = threadIdx.x;
    float s = 0.f;
    #pragma unroll 4
    for (int j = 0; j < 128; j++)
        s += Wo[k * 128 + j] * ctxW[(128 + j) * 128 + n];
    __nv_bfloat16 h = __float2bfloat16(s);
    g_Wcct_h[n * 128 + k] = h;
    g_Wcct_l[n * 128 + k] = __float2bfloat16(s - __bfloat162float(h));
}

__global__ void bcc_kernel(const float* __restrict__ bo, const float* __restrict__ ctxW,
                           const float* __restrict__ ctxb) {
    int c = threadIdx.x;
    float s = ctxb[c];
    for (int k = 0; k < 128; k++) s += bo[k] * ctxW[(128 + k) * 128 + c];
    g_bcc[c] = s;
}

__global__ void convert_split_kernel(const float* __restrict__ x,
                                     __nv_bfloat16* __restrict__ h, __nv_bfloat16* __restrict__ l,
                                     int n4) {
    int i = blockIdx.x * blockDim.x + threadIdx.x;
    if (i >= n4) return;
    float4 v = ((const float4*)x)[i];
    store_split4(v, h + (size_t)i * 4, l + (size_t)i * 4);
}

__global__ void build_query_kernel(const float* __restrict__ sq, const float* __restrict__ h1) {
    int i = blockIdx.x * blockDim.x + threadIdx.x;
    if (i >= R_Q * Hd / 4) return;
    int c4 = (i & 31) << 2;
    int r  = i >> 5;
    int t  = (r / Nd) % Td;
    int b  = r / (Td * Nd);
    int n  = r % Nd;
    float4 a  = *(const float4*)(sq + t * Hd + c4);
    float4 hh = *(const float4*)(h1 + ((size_t)(b * Nd + n)) * Hd + c4);
    float4 v  = make_float4(a.x + hh.x, a.y + hh.y, a.z + hh.z, a.w + hh.w);
    store_split4(v, g_query_h + (size_t)r * Hd + c4, g_query_l + (size_t)r * Hd + c4);
}

// ---------------- attention: one block per (b,n) ----------------
#define ATTN_SMEM ((24*132 + 168*132 + 96*168) * 4)

__global__ void __launch_bounds__(256) attn_kernel(
    const float* __restrict__ Q, const float* __restrict__ KV,
    float* __restrict__ attn_out,
    __nv_bfloat16* __restrict__ ctx_h, __nv_bfloat16* __restrict__ ctx_l)
{
    const int n = blockIdx.x;
    const int b = blockIdx.y;
    extern __shared__ __align__(16) char dynsm[];
    float* sm = (float*)dynsm;
    float* sQ = sm;
    float* sK = sm + 24*132;
    float* sS = sK + 168*132;
    const int tid = threadIdx.x;

    {
        const float* qb = Q + ((size_t)(b * Td) * Nd + n) * Hd;
        for (int i = tid; i < Td * 32; i += 256) {
            int t = i >> 5, c4 = (i & 31) << 2;
            *(float4*)&sQ[t*132 + c4] = *(const float4*)(qb + (size_t)t * Nd * Hd + c4);
        }
    }
    {
        const float* kb = KV + ((size_t)(b * Sd) * Nd + n) * 256;
        for (int i = tid; i < Sd * 32; i += 256) {
            int s = i >> 5, c4 = (i & 31) << 2;
            *(float4*)&sK[s*132 + c4] = *(const float4*)(kb + (size_t)s * Nd * 256 + c4);
        }
    }
    __syncthreads();

    {
        const int hg  = tid >> 6;
        const int i_t = (tid >> 3) & 7;
        const int j_s = tid & 7;
        float acc[3][21];
        #pragma unroll
        for (int a = 0; a < 3; a++)
            #pragma unroll
            for (int c = 0; c < 21; c++) acc[a][c] = 0.f;
        #pragma unroll
        for (int d4 = 0; d4 < 8; d4++) {
            float4 q[3];
            #pragma unroll
            for (int a = 0; a < 3; a++)
                q[a] = *(const float4*)&sQ[(i_t + 8*a)*132 + hg*32 + d4*4];
            #pragma unroll
            for (int c = 0; c < 21; c++) {
                float4 k = *(const float4*)&sK[(j_s + 8*c)*132 + hg*32 + d4*4];
                #pragma unroll
                for (int a = 0; a < 3; a++)
                    acc[a][c] += q[a].x*k.x + q[a].y*k.y + q[a].z*k.z + q[a].w*k.w;
            }
        }
        const float scale = 0.17677669529663687f;
        #pragma unroll
        for (int a = 0; a < 3; a++)
            #pragma unroll
            for (int c = 0; c < 21; c++)
                sS[((i_t + 8*a)*4 + hg)*168 + (j_s + 8*c)] = acc[a][c] * scale;
    }
    __syncthreads();

    {
        const float* vb = KV + ((size_t)(b * Sd) * Nd + n) * 256 + 128;
        for (int i = tid; i < Sd * 32; i += 256) {
            int s = i >> 5, c4 = (i & 31) << 2;
            *(float4*)&sK[s*132 + c4] = *(const float4*)(vb + (size_t)s * Nd * 256 + c4);
        }
    }

    {
        const int w = tid >> 5, lane = tid & 31;
        for (int rr = 0; rr < 12; rr++) {
            int row = w + (rr << 3);
            float* Sr = sS + row * 168;
            float vals[6];
            float vmax = -1e30f;
            #pragma unroll
            for (int k = 0; k < 6; k++) {
                int s = lane + (k << 5);
                vals[k] = (s < 168) ? Sr[s] : -1e30f;
                vmax = fmaxf(vmax, vals[k]);
            }
            #pragma unroll
            for (int o = 16; o > 0; o >>= 1) vmax = fmaxf(vmax, __shfl_xor_sync(~0u, vmax, o));
            float sum = 0.f;
            #pragma unroll
            for (int k = 0; k < 6; k++) {
                int s = lane + (k << 5);
                float e = (s < 168) ? expf(vals[k] - vmax) : 0.f;
                vals[k] = e; sum += e;
            }
            #pragma unroll
            for (int o = 16; o > 0; o >>= 1) sum += __shfl_xor_sync(~0u, sum, o);
            float inv = 1.f / sum;
            int t = row >> 2, h = row & 3;
            float* outp = attn_out + ((((size_t)(b * Td + t) * NHd + h) * Nd + n) * Sd);
            #pragma unroll
            for (int k = 0; k < 6; k++) {
                int s = lane + (k << 5);
                if (s < 168) { float p = vals[k] * inv; Sr[s] = p; outp[s] = p; }
            }
        }
    }
    __syncthreads();

    {
        const int cq = tid & 31;
        const int tg = tid >> 5;
        const int c0 = cq << 2;
        const int h  = c0 >> 5;
        float acc2[3][4];
        #pragma unroll
        for (int a = 0; a < 3; a++)
            #pragma unroll
            for (int j = 0; j < 4; j++) acc2[a][j] = 0.f;
        #pragma unroll 4
        for (int s = 0; s < 168; s++) {
            float4 v = *(const float4*)&sK[s*132 + c0];
            #pragma unroll
            for (int a = 0; a < 3; a++) {
                int t = tg + (a << 3);
                float p = sS[(t*4 + h)*168 + s];
                acc2[a][0] += p * v.x; acc2[a][1] += p * v.y;
                acc2[a][2] += p * v.z; acc2[a][3] += p * v.w;
            }
        }
        #pragma unroll
        for (int a = 0; a < 3; a++) {
            int t = tg + (a << 3);
            size_t base = ((size_t)(b * Td + t) * Nd + n) * Hd + c0;
            float4 v = make_float4(acc2[a][0], acc2[a][1], acc2[a][2], acc2[a][3]);
            store_split4(v, ctx_h + base, ctx_l + base);
        }
    }
}

// ---------------- layernorm (comb -> xln) ----------------
__global__ void ln_kernel(const float* __restrict__ x, const float* __restrict__ g,
                          const float* __restrict__ bt,
                          __nv_bfloat16* __restrict__ yh, __nv_bfloat16* __restrict__ yl) {
    int w = threadIdx.x >> 5, lane = threadIdx.x & 31;
    int row = blockIdx.x * 8 + w;
    const float* xr = x + (size_t)row * 128;
    float4 v = *(const float4*)(xr + lane * 4);
    float s  = v.x + v.y + v.z + v.w;
    float sq = v.x*v.x + v.y*v.y + v.z*v.z + v.w*v.w;
    #pragma unroll
    for (int o = 16; o > 0; o >>= 1) {
        s  += __shfl_xor_sync(~0u, s,  o);
        sq += __shfl_xor_sync(~0u, sq, o);
    }
    float m   = s * (1.f / 128.f);
    float var = sq * (1.f / 128.f) - m * m;
    float inv = rsqrtf(var + 1e-5f);
    float4 gg = *(const float4*)(g + lane * 4);
    float4 bb = *(const float4*)(bt + lane * 4);
    float4 o4;
    o4.x = (v.x - m) * inv * gg.x + bb.x;
    o4.y = (v.y - m) * inv * gg.y + bb.y;
    o4.z = (v.z - m) * inv * gg.z + bb.z;
    o4.w = (v.w - m) * inv * gg.w + bb.w;
    store_split4(o4, yh + (size_t)row * 128 + lane * 4, yl + (size_t)row * 128 + lane * 4);
}

// ---------------- G[b,m,:] = sum_n adj[m,n]*hWh[b,n,:] + bias ----------------
__global__ void agg_kernel(const float* __restrict__ adj, const float* __restrict__ hWh,
                           const float* __restrict__ bv, float* __restrict__ G) {
    __shared__ float sA[8][200];
    int b = blockIdx.y, m0 = blockIdx.x * 8;
    int tid = threadIdx.x;
    for (int i = tid; i < 8 * 200; i += 512) {
        int m = i / 200, nn = i % 200;
        sA[m][nn] = adj[(m0 + m) * 200 + nn];
    }
    __syncthreads();
    int c = tid;
    float acc[8];
    #pragma unroll
    for (int m = 0; m < 8; m++) acc[m] = 0.f;
    const float* hb = hWh + (size_t)b * 200 * 512 + c;
    for (int nn = 0; nn < 200; nn++) {
        float v = hb[(size_t)nn * 512];
        #pragma unroll
        for (int m = 0; m < 8; m++) acc[m] += sA[m][nn] * v;
    }
    float bb = bv[c];
    #pragma unroll
    for (int m = 0; m < 8; m++)
        G[((size_t)b * 200 + m0 + m) * 512 + c] = acc[m] + bb;
}

// ---------------- fused LSTM act (layer 0) + LN(lng1,lnb1): warp per row ----------------
__global__ void act_ln_kernel(const float* __restrict__ gates, const float* __restrict__ G,
                              const float* __restrict__ cin,
                              const float* __restrict__ lng, const float* __restrict__ lnb,
                              float* __restrict__ x1out,
                              __nv_bfloat16* __restrict__ yh, __nv_bfloat16* __restrict__ yl) {
    int w = threadIdx.x >> 5, lane = threadIdx.x & 31;
    int r = blockIdx.x * 8 + w;
    int h0 = lane * 4;
    int b = r / (Td * Nd);
    int n = r % Nd;
    size_t gr = (size_t)r * 512 + h0;
    size_t gb = ((size_t)(b * Nd) + n) * 512 + h0;
    float4 gi = *(const float4*)(gates + gr);
    float4 gf = *(const float4*)(gates + gr + 128);
    float4 gg = *(const float4*)(gates + gr + 256);
    float4 go = *(const float4*)(gates + gr + 384);
    float4 Gi = *(const float4*)(G + gb);
    float4 Gf = *(const float4*)(G + gb + 128);
    float4 Gg = *(const float4*)(G + gb + 256);
    float4 Go = *(const float4*)(G + gb + 384);
    float4 cc = *(const float4*)(cin + ((size_t)(b * Nd) + n) * 128 + h0);
    float x[4];
    float cn;
    cn = sigmoidf_(gf.x + Gf.x) * cc.x + sigmoidf_(gi.x + Gi.x) * tanhf(gg.x + Gg.x);
    x[0] = sigmoidf_(go.x + Go.x) * tanhf(cn);
    cn = sigmoidf_(gf.y + Gf.y) * cc.y + sigmoidf_(gi.y + Gi.y) * tanhf(gg.y + Gg.y);
    x[1] = sigmoidf_(go.y + Go.y) * tanhf(cn);
    cn = sigmoidf_(gf.z + Gf.z) * cc.z + sigmoidf_(gi.z + Gi.z) * tanhf(gg.z + Gg.z);
    x[2] = sigmoidf_(go.z + Go.z) * tanhf(cn);
    cn = sigmoidf_(gf.w + Gf.w) * cc.w + sigmoidf_(gi.w + Gi.w) * tanhf(gg.w + Gg.w);
    x[3] = sigmoidf_(go.w + Go.w) * tanhf(cn);
    *(float4*)(x1out + (size_t)r * 128 + h0) = make_float4(x[0], x[1], x[2], x[3]);
    float s = x[0] + x[1] + x[2] + x[3];
    float sq = x[0]*x[0] + x[1]*x[1] + x[2]*x[2] + x[3]*x[3];
    #pragma unroll
    for (int o = 16; o > 0; o >>= 1) {
        s  += __shfl_xor_sync(~0u, s,  o);
        sq += __shfl_xor_sync(~0u, sq, o);
    }
    float m   = s * (1.f / 128.f);
    float var = sq * (1.f / 128.f) - m * m;
    float inv = rsqrtf(var + 1e-5f);
    float4 gv = *(const float4*)(lng + h0);
    float4 bvv = *(const float4*)(lnb + h0);
    float4 o4;
    o4.x = (x[0] - m) * inv * gv.x + bvv.x;
    o4.y = (x[1] - m) * inv * gv.y + bvv.y;
    o4.z = (x[2] - m) * inv * gv.z + bvv.z;
    o4.w = (x[3] - m) * inv * gv.w + bvv.w;
    store_split4(o4, yh + (size_t)r * 128 + h0, yl + (size_t)r * 128 + h0);
}

// ---------------- fused LSTM act (layer 1) + residual + preds: warp per row ----------------
__global__ void act_preds_kernel(const float* __restrict__ gates, const float* __restrict__ G,
                                 const float* __restrict__ cin, const float* __restrict__ resid,
                                 const float* __restrict__ W, const float* __restrict__ ob,
                                 float* __restrict__ out) {
    int w = threadIdx.x >> 5, lane = threadIdx.x & 31;
    int r = blockIdx.x * 8 + w;
    int h0 = lane * 4;
    int b = r / (Td * Nd);
    int n = r % Nd;
    size_t gr = (size_t)r * 512 + h0;
    size_t gb = ((size_t)(b * Nd) + n) * 512 + h0;
    float4 gi = *(const float4*)(gates + gr);
    float4 gf = *(const float4*)(gates + gr + 128);
    float4 gg = *(const float4*)(gates + gr + 256);
    float4 go = *(const float4*)(gates + gr + 384);
    float4 Gi = *(const float4*)(G + gb);
    float4 Gf = *(const float4*)(G + gb + 128);
    float4 Gg = *(const float4*)(G + gb + 256);
    float4 Go = *(const float4*)(G + gb + 384);
    float4 cc = *(const float4*)(cin + ((size_t)(b * Nd) + n) * 128 + h0);
    float4 rv = *(const float4*)(resid + (size_t)r * 128 + h0);
    float4 ww = *(const float4*)(W + h0);
    float x, cn, s = 0.f;
    cn = sigmoidf_(gf.x + Gf.x) * cc.x + sigmoidf_(gi.x + Gi.x) * tanhf(gg.x + Gg.x);
    x  = sigmoidf_(go.x + Go.x) * tanhf(cn) + rv.x;  s += x * ww.x;
    cn = sigmoidf_(gf.y + Gf.y) * cc.y + sigmoidf_(gi.y + Gi.y) * tanhf(gg.y + Gg.y);
    x  = sigmoidf_(go.y + Go.y) * tanhf(cn) + rv.y;  s += x * ww.y;
    cn = sigmoidf_(gf.z + Gf.z) * cc.z + sigmoidf_(gi.z + Gi.z) * tanhf(gg.z + Gg.z);
    x  = sigmoidf_(go.z + Go.z) * tanhf(cn) + rv.z;  s += x * ww.z;
    cn = sigmoidf_(gf.w + Gf.w) * cc.w + sigmoidf_(gi.w + Gi.w) * tanhf(gg.w + Gg.w);
    x  = sigmoidf_(go.w + Go.w) * tanhf(cn) + rv.w;  s += x * ww.w;
    #pragma unroll
    for (int o = 16; o > 0; o >>= 1) s += __shfl_xor_sync(~0u, s, o);
    if (lane == 0) out[r] = s + ob[0];
}

// ---------------- launch ----------------
#define GS(p, sym) cudaGetSymbolAddress((void**)&p, sym)

extern "C" void kernel_launch(void* const* d_in, const int* in_sizes, int n_in,
                              void* d_out, int out_size) {
    const float* enc  = (const float*)d_in[0];
    const float* h0   = (const float*)d_in[1];
    const float* c0   = (const float*)d_in[2];
    const float* h1   = (const float*)d_in[3];
    const float* c1   = (const float*)d_in[4];
    const float* adj  = (const float*)d_in[5];
    const float* sq   = (const float*)d_in[6];
    const float* Wq   = (const float*)d_in[7];
    const float* bq   = (const float*)d_in[8];
    const float* Wk   = (const float*)d_in[9];
    const float* bk   = (const float*)d_in[10];
    const float* Wv   = (const float*)d_in[11];
    const float* bv   = (const float*)d_in[12];
    const float* Wo   = (const float*)d_in[13];
    const float* bo   = (const float*)d_in[14];
    const float* ctxW = (const float*)d_in[15];
    const float* ctxb = (const float*)d_in[16];
    const float* Wx0  = (const float*)d_in[17];
    const float* Wh0  = (const float*)d_in[18];
    const float* b0   = (const float*)d_in[19];
    const float* lng0 = (const float*)d_in[20];
    const float* lnb0 = (const float*)d_in[21];
    const float* Wx1  = (const float*)d_in[22];
    const float* Wh1  = (const float*)d_in[23];
    const float* b1   = (const float*)d_in[24];
    const float* lng1 = (const float*)d_in[25];
    const float* lnb1 = (const float*)d_in[26];
    const float* outW = (const float*)d_in[27];
    const float* outb = (const float*)d_in[28];

    float* out      = (float*)d_out;
    float* attn_out = out + R_Q;

    __nv_bfloat16 *pQh, *pQl, *pCh, *pCl, *pXh, *pXl;
    __nv_bfloat16 *pH0h, *pH0l, *pH1h, *pH1l;
    __nv_bfloat16 *pWqh, *pWql, *pWkvh, *pWkvl, *pWth, *pWtl, *pWcch, *pWccl;
    __nv_bfloat16 *pWx0h, *pWx0l, *pWh0h, *pWh0l, *pWx1h, *pWx1l, *pWh1h, *pWh1l;
    float *pQf, *pKV, *pComb, *pGates, *pX1, *pHWh, *pG0, *pG1, *pBkv, *pBcc;
    GS(pQh, g_query_h); GS(pQl, g_query_l);
    GS(pCh, g_ctx_h);   GS(pCl, g_ctx_l);
    GS(pXh, g_xln_h);   GS(pXl, g_xln_l);
    GS(pH0h, g_h0_h);   GS(pH0l, g_h0_l);
    GS(pH1h, g_h1_h);   GS(pH1l, g_h1_l);
    GS(pWqh, g_Wqt_h);  GS(pWql, g_Wqt_l);
    GS(pWkvh, g_Wkvt_h); GS(pWkvl, g_Wkvt_l);
    GS(pWth, g_Wtop_h); GS(pWtl, g_Wtop_l);
    GS(pWcch, g_Wcct_h); GS(pWccl, g_Wcct_l);
    GS(pWx0h, g_Wx0t_h); GS(pWx0l, g_Wx0t_l);
    GS(pWh0h, g_Wh0t_h); GS(pWh0l, g_Wh0t_l);
    GS(pWx1h, g_Wx1t_h); GS(pWx1l, g_Wx1t_l);
    GS(pWh1h, g_Wh1t_h); GS(pWh1l, g_Wh1t_l);
    GS(pQf, g_Q);       GS(pKV, g_KV);
    GS(pComb, g_comb);  GS(pGates, g_gates);
    GS(pX1, g_x1);
    GS(pHWh, g_hWh);    GS(pG0, g_G0);    GS(pG1, g_G1);
    GS(pBkv, g_bkv);    GS(pBcc, g_bcc);

    cudaFuncSetAttribute(gemm_mma_kernel, cudaFuncAttributeMaxDynamicSharedMemorySize, GEMM_SMEM);
    cudaFuncSetAttribute(gemm_kv_kernel,  cudaFuncAttributeMaxDynamicSharedMemorySize, KV_SMEM);
    cudaFuncSetAttribute(attn_kernel,     cudaFuncAttributeMaxDynamicSharedMemorySize, ATTN_SMEM);

    // --- weight prep ---
    wsplit_kernel<<<dim3(4, 4),  dim3(32, 8)>>>(Wk, 128, pWkvh, pWkvl);
    wsplit_kernel<<<dim3(4, 4),  dim3(32, 8)>>>(Wv, 128, pWkvh + 128*128, pWkvl + 128*128);
    bkv_kernel<<<1, 256>>>(bk, bv);
    wsplit_kernel<<<dim3(4, 4),  dim3(32, 8)>>>(Wq, 128, pWqh, pWql);
    wsplit_kernel<<<dim3(4, 4),  dim3(32, 8)>>>(ctxW, 128, pWth, pWtl);
    wcct_kernel<<<128, 128>>>(Wo, ctxW);
    bcc_kernel<<<1, 128>>>(bo, ctxW, ctxb);
    wsplit_kernel<<<dim3(16, 4), dim3(32, 8)>>>(Wx0, 512, pWx0h, pWx0l);
    wsplit_kernel<<<dim3(16, 4), dim3(32, 8)>>>(Wh0, 512, pWh0h, pWh0l);
    wsplit_kernel<<<dim3(16, 4), dim3(32, 8)>>>(Wx1, 512, pWx1h, pWx1l);
    wsplit_kernel<<<dim3(16, 4), dim3(32, 8)>>>(Wh1, 512, pWh1h, pWh1l);

    // --- activation conversions ---
    convert_split_kernel<<<400, 256>>>(h0, pH0h, pH0l, 3200 * 32);
    convert_split_kernel<<<400, 256>>>(h1, pH1h, pH1l, 3200 * 32);
    build_query_kernel<<<(R_Q * 32 + 255) / 256, 256>>>(sq, h1);

    // --- projections ---
    gemm_mma_kernel<<<dim3(1, 600), 256, GEMM_SMEM>>>(pQh, pQl, pWqh, pWql, pQf, bq, 128, 0);
    gemm_kv_kernel<<<4200, 256, KV_SMEM>>>(enc, pWkvh, pWkvl, pKV, pBkv);

    // --- attention ---
    attn_kernel<<<dim3(Nd, Bd), 256, ATTN_SMEM>>>(pQf, pKV, attn_out, pCh, pCl);

    // --- combined = query@ctxW_top + ctx@Wcc + bcc ---
    gemm_mma_kernel<<<dim3(1, 600), 256, GEMM_SMEM>>>(pQh, pQl, pWth, pWtl, pComb, pBcc, 128, 0);
    gemm_mma_kernel<<<dim3(1, 600), 256, GEMM_SMEM>>>(pCh, pCl, pWcch, pWccl, pComb, (const float*)0, 128, 1);

    // --- layer 0 ---
    gemm_mma_kernel<<<dim3(4, 25), 256, GEMM_SMEM>>>(pH0h, pH0l, pWh0h, pWh0l, pHWh, (const float*)0, 512, 0);
    agg_kernel<<<dim3(25, Bd), 512>>>(adj, pHWh, b0, pG0);
    ln_kernel<<<R_Q / 8, 256>>>(pComb, lng0, lnb0, pXh, pXl);
    gemm_mma_kernel<<<dim3(4, 600), 256, GEMM_SMEM>>>(pXh, pXl, pWx0h, pWx0l, pGates, (const float*)0, 512, 0);
    act_ln_kernel<<<R_Q / 8, 256>>>(pGates, pG0, c0, lng1, lnb1, pX1, pXh, pXl);

    // --- layer 1 (+ residual + preds, fused) ---
    gemm_mma_kernel<<<dim3(4, 25), 256, GEMM_SMEM>>>(pH1h, pH1l, pWh1h, pWh1l, pHWh, (const float*)0, 512, 0);
    agg_kernel<<<dim3(25, Bd), 512>>>(adj, pHWh, b1, pG1);
    gemm_mma_kernel<<<dim3(4, 600), 256, GEMM_SMEM>>>(pXh, pXl, pWx1h, pWx1l, pGates, (const float*)0, 512, 0);
    act_preds_kernel<<<R_Q / 8, 256>>>(pGates, pG1, c1, pX1, outW, outb, out);
}